// round 10
// baseline (speedup 1.0000x reference)
#include <cuda_runtime.h>
#include <cuda_bf16.h>
#include <mma.h>
#include <math.h>
#include <stdint.h>

using namespace nvcuda;

#define B_   4
#define C_   256
#define L_   4096
#define G_   8
#define NH   4
#define HD   64
#define EPSV 1e-5f
#define EP   72    // gemm epilogue staging pitch (floats)
#define WP   40    // gemm W tile pitch (bf16)
#define XP   80    // gemm X tile pitch (bf16)
#define WBUF (128 * WP * 2)   // 10240 B
#define XBUF (32 * XP * 2)    //  5120 B
#define TPB  80    // attn tile row pitch (bytes)
#define TBUF (64 * TPB)       //  5120 B
#define OP   72    // attn O staging pitch (floats)
#define LOG2E 1.4426950408889634f
#define ONES_BF16X2 0x3F803F80u

// Scratch (device globals)
__device__ float         g_xn  [B_ * C_ * L_];
__device__ __nv_bfloat16 g_xnh [B_ * C_ * L_];
__device__ __nv_bfloat16 g_qkvh[B_ * 3 * C_ * L_];
__device__ __nv_bfloat16 g_atth[B_ * C_ * L_];
__device__ float         g_part[B_ * G_ * 8 * 2];
__device__ __nv_bfloat16 g_wqh [3 * C_ * C_];
__device__ __nv_bfloat16 g_wph [C_ * C_];

// ---------------------------------------------------------------------------
__device__ __forceinline__ uint32_t pack_bf16(float lo, float hi) {
    __nv_bfloat162 p = __floats2bfloat162_rn(lo, hi);
    return *reinterpret_cast<uint32_t*>(&p);
}
__device__ __forceinline__ float ex2f(float x) {
    float y; asm("ex2.approx.f32 %0, %1;" : "=f"(y) : "f"(x)); return y;
}
__device__ __forceinline__ void mma16(float* d, const uint32_t* a, uint32_t b0, uint32_t b1) {
    asm volatile(
        "mma.sync.aligned.m16n8k16.row.col.f32.bf16.bf16.f32 "
        "{%0,%1,%2,%3}, {%4,%5,%6,%7}, {%8,%9}, {%0,%1,%2,%3};"
        : "+f"(d[0]), "+f"(d[1]), "+f"(d[2]), "+f"(d[3])
        : "r"(a[0]), "r"(a[1]), "r"(a[2]), "r"(a[3]), "r"(b0), "r"(b1));
}
__device__ __forceinline__ void ldsm4(uint32_t& r0, uint32_t& r1, uint32_t& r2, uint32_t& r3,
                                      uint32_t saddr) {
    asm volatile("ldmatrix.sync.aligned.m8n8.x4.shared.b16 {%0,%1,%2,%3}, [%4];"
        : "=r"(r0), "=r"(r1), "=r"(r2), "=r"(r3) : "r"(saddr));
}
__device__ __forceinline__ void ldsm4t(uint32_t& r0, uint32_t& r1, uint32_t& r2, uint32_t& r3,
                                       uint32_t saddr) {
    asm volatile("ldmatrix.sync.aligned.m8n8.x4.trans.shared.b16 {%0,%1,%2,%3}, [%4];"
        : "=r"(r0), "=r"(r1), "=r"(r2), "=r"(r3) : "r"(saddr));
}
__device__ __forceinline__ void cpa16(uint32_t dst, const void* src) {
    asm volatile("cp.async.cg.shared.global [%0], [%1], 16;" :: "r"(dst), "l"(src));
}
__device__ __forceinline__ void cpa_commit() {
    asm volatile("cp.async.commit_group;");
}
template<int N>
__device__ __forceinline__ void cpa_wait() {
    asm volatile("cp.async.wait_group %0;" :: "n"(N));
}

// ---------------------------------------------------------------------------
// GroupNorm pass 1
// ---------------------------------------------------------------------------
__global__ void gn_reduce(const float* __restrict__ x, float* __restrict__ part) {
    const int blk = blockIdx.x;
    const int bg = blk >> 3, sub = blk & 7;
    const int SL = (C_ / G_) * L_ / 8;
    const float* xp = x + (size_t)bg * (C_ / G_) * L_ + (size_t)sub * SL;

    float s = 0.f, s2 = 0.f;
    for (int i = threadIdx.x * 4; i < SL; i += blockDim.x * 4) {
        float4 v = *reinterpret_cast<const float4*>(xp + i);
        s  += v.x + v.y + v.z + v.w;
        s2 += v.x * v.x + v.y * v.y + v.z * v.z + v.w * v.w;
    }
    #pragma unroll
    for (int o = 16; o; o >>= 1) {
        s  += __shfl_xor_sync(~0u, s,  o);
        s2 += __shfl_xor_sync(~0u, s2, o);
    }
    __shared__ float rs[8], rs2[8];
    const int wid = threadIdx.x >> 5;
    if ((threadIdx.x & 31) == 0) { rs[wid] = s; rs2[wid] = s2; }
    __syncthreads();
    if (threadIdx.x == 0) {
        float ts = 0.f, ts2 = 0.f;
        #pragma unroll
        for (int i = 0; i < 8; i++) { ts += rs[i]; ts2 += rs2[i]; }
        part[blk * 2 + 0] = ts;
        part[blk * 2 + 1] = ts2;
    }
}

// ---------------------------------------------------------------------------
// GroupNorm pass 2: fp32 xn + bf16 xnh; ALSO converts weights to bf16
// (grid 256 x 256 threads x 4 elems = 262144 = 4*C*C total weight elems)
// ---------------------------------------------------------------------------
__global__ void gn_apply(const float* __restrict__ x,
                         const float* __restrict__ part,
                         const float* __restrict__ gamma,
                         const float* __restrict__ beta,
                         float* __restrict__ xn,
                         __nv_bfloat16* __restrict__ xnh,
                         const float* __restrict__ qkv_w,
                         const float* __restrict__ proj_w,
                         __nv_bfloat16* __restrict__ wqh,
                         __nv_bfloat16* __restrict__ wph) {
    const int blk = blockIdx.x;
    const int bg = blk >> 3, sub = blk & 7;
    const int g = bg & (G_ - 1);
    const int SL = (C_ / G_) * L_ / 8;
    const int n = (C_ / G_) * L_;

    // fused weight conversion
    {
        const int wi = (blk * 256 + threadIdx.x) * 4;
        const float* src; __nv_bfloat16* dst; int off;
        if (wi < 3 * C_ * C_) { src = qkv_w; dst = wqh; off = wi; }
        else                  { src = proj_w; dst = wph; off = wi - 3 * C_ * C_; }
        float4 v = *reinterpret_cast<const float4*>(src + off);
        uint2 pk;
        pk.x = pack_bf16(v.x, v.y);
        pk.y = pack_bf16(v.z, v.w);
        *reinterpret_cast<uint2*>(dst + off) = pk;
    }

    float ts = 0.f, ts2 = 0.f;
    #pragma unroll
    for (int i = 0; i < 8; i++) {
        ts  += part[(bg * 8 + i) * 2 + 0];
        ts2 += part[(bg * 8 + i) * 2 + 1];
    }
    const float mean = ts / (float)n;
    const float inv  = rsqrtf(ts2 / (float)n - mean * mean + EPSV);

    const size_t base = (size_t)bg * (C_ / G_) * L_ + (size_t)sub * SL;
    const float* xp = x + base;
    float* yp = xn + base;
    __nv_bfloat16* hp = xnh + base;
    const int off0 = sub * SL;
    for (int i = threadIdx.x * 4; i < SL; i += blockDim.x * 4) {
        const int c = g * (C_ / G_) + ((off0 + i) >> 12);
        const float ga = gamma[c], be = beta[c];
        float4 v = *reinterpret_cast<const float4*>(xp + i);
        float4 o;
        o.x = (v.x - mean) * inv * ga + be;
        o.y = (v.y - mean) * inv * ga + be;
        o.z = (v.z - mean) * inv * ga + be;
        o.w = (v.w - mean) * inv * ga + be;
        *reinterpret_cast<float4*>(yp + i) = o;
        uint2 pk;
        pk.x = pack_bf16(o.x, o.y);
        pk.y = pack_bf16(o.z, o.w);
        *reinterpret_cast<uint2*>(hp + i) = pk;
    }
}

// ---------------------------------------------------------------------------
// bf16 wmma GEMM: 128m x 64n tile, 3-stage cp.async pipeline, 256 threads,
// 8 warps as 4m x 2n of 32x32. One barrier per 32-k step.
// ---------------------------------------------------------------------------
template<bool RESID, bool QKVOUT>
__global__ __launch_bounds__(256)
void gemm_bf16(const __nv_bfloat16* __restrict__ Wh,
               const float* __restrict__ bias,
               const __nv_bfloat16* __restrict__ X,
               void* __restrict__ Yv,
               const float* __restrict__ R,
               int Mtot, int KDIM) {
    const int n0 = blockIdx.x * 64;
    const int m0 = blockIdx.y * 128;
    const int b  = blockIdx.z;
    const __nv_bfloat16* Xb = X + (size_t)b * KDIM * L_;

    __shared__ uint8_t smraw[3 * (WBUF + XBUF)];   // 46080 B; epilogue reuses
    const uint32_t sb = (uint32_t)__cvta_generic_to_shared(smraw);

    const int tid = threadIdx.x;
    const int wid = tid >> 5;
    const int wm = wid >> 1, wn = wid & 1;

    // loader indices
    const int wr0 = tid >> 1, wk0 = (tid & 1) * 16;   // W: 2 chunks per thread
    const int xr  = tid >> 3, xn8 = (tid & 7) * 8;    // X: 1 chunk per thread (all 256)

    const int NS = KDIM / 32;

    auto issue = [&](int s) {
        const int k0 = s * 32;
        const uint32_t wbase = sb + (s % 3) * WBUF;
        const uint32_t xbase = sb + 3 * WBUF + (s % 3) * XBUF;
        // W tile: 128 x 32 bf16; 2 chunks per thread (16B = 8 bf16)
        cpa16(wbase + (wr0 * WP + wk0) * 2,
              Wh + (size_t)(m0 + wr0) * KDIM + k0 + wk0);
        cpa16(wbase + (wr0 * WP + wk0 + 8) * 2,
              Wh + (size_t)(m0 + wr0) * KDIM + k0 + wk0 + 8);
        // X tile: 32 x 64 bf16 = 256 chunks; all 256 threads, one each
        cpa16(xbase + (xr * XP + xn8) * 2,
              Xb + (size_t)(k0 + xr) * L_ + n0 + xn8);
    };

    wmma::fragment<wmma::accumulator, 16, 16, 16, float> c00, c01, c10, c11;
    wmma::fill_fragment(c00, 0.f); wmma::fill_fragment(c01, 0.f);
    wmma::fill_fragment(c10, 0.f); wmma::fill_fragment(c11, 0.f);

    issue(0); cpa_commit();
    issue(1); cpa_commit();

    for (int s = 0; s < NS; s++) {
        cpa_wait<1>();
        __syncthreads();
        if (s + 2 < NS) issue(s + 2);
        cpa_commit();

        const __nv_bfloat16* Ws = reinterpret_cast<const __nv_bfloat16*>(smraw + (s % 3) * WBUF);
        const __nv_bfloat16* Xs = reinterpret_cast<const __nv_bfloat16*>(smraw + 3 * WBUF + (s % 3) * XBUF);
        #pragma unroll
        for (int ks = 0; ks < 32; ks += 16) {
            wmma::fragment<wmma::matrix_a, 16, 16, 16, __nv_bfloat16, wmma::row_major> a0, a1;
            wmma::fragment<wmma::matrix_b, 16, 16, 16, __nv_bfloat16, wmma::row_major> b0, b1;
            wmma::load_matrix_sync(a0, &Ws[(wm * 32) * WP + ks], WP);
            wmma::load_matrix_sync(a1, &Ws[(wm * 32 + 16) * WP + ks], WP);
            wmma::load_matrix_sync(b0, &Xs[ks * XP + wn * 32], XP);
            wmma::load_matrix_sync(b1, &Xs[ks * XP + wn * 32 + 16], XP);
            wmma::mma_sync(c00, a0, b0, c00);
            wmma::mma_sync(c01, a0, b1, c01);
            wmma::mma_sync(c10, a1, b0, c10);
            wmma::mma_sync(c11, a1, b1, c11);
        }
    }
    __syncthreads();

    // epilogue: stage fp32 accumulators in smem [128][EP]
    float* smf = reinterpret_cast<float*>(smraw);
    wmma::store_matrix_sync(&smf[(wm * 32)      * EP + wn * 32],      c00, EP, wmma::mem_row_major);
    wmma::store_matrix_sync(&smf[(wm * 32)      * EP + wn * 32 + 16], c01, EP, wmma::mem_row_major);
    wmma::store_matrix_sync(&smf[(wm * 32 + 16) * EP + wn * 32],      c10, EP, wmma::mem_row_major);
    wmma::store_matrix_sync(&smf[(wm * 32 + 16) * EP + wn * 32 + 16], c11, EP, wmma::mem_row_major);
    __syncthreads();
    {
        const int m = tid >> 1, nn = (tid & 1) * 32;
        const float bv = bias[m0 + m];
        const size_t orow = (size_t)(m0 + m) * L_ + n0 + nn;
        if (QKVOUT) {
            __nv_bfloat16* Ybh = (__nv_bfloat16*)Yv + (size_t)b * Mtot * L_;
            const float sc = (m0 + m < C_) ? 0.125f * LOG2E : 1.0f;
            #pragma unroll
            for (int i = 0; i < 32; i += 4) {
                float4 v = *reinterpret_cast<const float4*>(&smf[m * EP + nn + i]);
                v.x = (v.x + bv) * sc; v.y = (v.y + bv) * sc;
                v.z = (v.z + bv) * sc; v.w = (v.w + bv) * sc;
                uint2 pk;
                pk.x = pack_bf16(v.x, v.y);
                pk.y = pack_bf16(v.z, v.w);
                *reinterpret_cast<uint2*>(Ybh + orow + i) = pk;
            }
        } else {
            float* Yb = (float*)Yv + (size_t)b * Mtot * L_;
            #pragma unroll
            for (int i = 0; i < 32; i += 4) {
                float4 v = *reinterpret_cast<const float4*>(&smf[m * EP + nn + i]);
                v.x += bv; v.y += bv; v.z += bv; v.w += bv;
                if (RESID) {
                    float4 r = *reinterpret_cast<const float4*>(&R[(size_t)b * Mtot * L_ + orow + i]);
                    v.x += r.x; v.y += r.y; v.z += r.z; v.w += r.w;
                }
                *reinterpret_cast<float4*>(Yb + orow + i) = v;
            }
        }
    }
}

// ---------------------------------------------------------------------------
// Flash attention: 64-query CTAs, 128 threads, occ 6 (wave-granularity fix).
// bf16 m16n8k16, cp.async 3-stage, ldmatrix, l via P@ones MMA. 32-key tiles.
// ---------------------------------------------------------------------------
__global__ __launch_bounds__(128, 6)
void attn_bf16(const __nv_bfloat16* __restrict__ qkv, __nv_bfloat16* __restrict__ out) {
    const int q0 = blockIdx.x * 64;
    const int h  = blockIdx.y;
    const int b  = blockIdx.z;

    extern __shared__ uint32_t smu[];
    const uint32_t sbase = (uint32_t)__cvta_generic_to_shared(smu);

    const int tid  = threadIdx.x;
    const int lane = tid & 31;
    const int w    = tid >> 5;        // 0..3
    const int lq   = lane >> 2;
    const int lr   = lane & 3;

    const size_t base = ((size_t)b * 3 * C_ + (size_t)h * HD) * L_;
    const uint16_t* Qp = (const uint16_t*)qkv + base;
    const uint16_t* Kp = Qp + (size_t)C_ * L_;
    const uint16_t* Vp = Qp + (size_t)2 * C_ * L_;

    uint32_t aQ[4][4];
    {
        const int qw = q0 + w * 16;
        #pragma unroll
        for (int c = 0; c < 4; c++) {
            const int d0 = c * 16 + 2 * lr;
            const uint16_t* qb = Qp + (size_t)d0 * L_ + qw;
            aQ[c][0] = (uint32_t)qb[lq]     | ((uint32_t)qb[(size_t)L_ + lq])     << 16;
            aQ[c][1] = (uint32_t)qb[lq + 8] | ((uint32_t)qb[(size_t)L_ + lq + 8]) << 16;
            const uint16_t* qc = qb + (size_t)8 * L_;
            aQ[c][2] = (uint32_t)qc[lq]     | ((uint32_t)qc[(size_t)L_ + lq])     << 16;
            aQ[c][3] = (uint32_t)qc[lq + 8] | ((uint32_t)qc[(size_t)L_ + lq + 8]) << 16;
        }
    }

    // loaders: 128 threads, 2 x 16B chunks each for K and V
    const int ld_d = tid >> 1;               // 0..63
    const int ld_c = (tid & 1) * 2;          // chunk base 0 or 2
    const uint16_t* kgp = Kp + (size_t)ld_d * L_ + ld_c * 8;
    const uint16_t* vgp = Vp + (size_t)ld_d * L_ + ld_c * 8;
    const uint32_t kds = sbase + ld_d * TPB + ld_c * 16;
    const uint32_t vds = sbase + 3 * TBUF + ld_d * TPB + ld_c * 16;

    const int mi = lane >> 3;
    const int r8 = lane & 7;
    const uint32_t kmat = sbase + ((mi & 1) * 8 + r8) * TPB + (mi >> 1) * 16;
    const uint32_t vmat = sbase + 3 * TBUF + ((mi >> 1) * 8 + r8) * TPB + (mi & 1) * 16;

    // prologue tiles 0,1
    cpa16(kds, kgp);               cpa16(kds + 16, kgp + 8);
    cpa16(vds, vgp);               cpa16(vds + 16, vgp + 8);
    cpa_commit();
    cpa16(kds + TBUF, kgp + 32);   cpa16(kds + TBUF + 16, kgp + 40);
    cpa16(vds + TBUF, vgp + 32);   cpa16(vds + TBUF + 16, vgp + 40);
    cpa_commit();

    float O[8][4] = {};
    float Lacc[4] = {};
    int bc = 0, bn = 2;

    for (int t = 0; t < L_ / 32; t++) {
        cpa_wait<1>();
        __syncthreads();

        if (t < L_ / 32 - 2) {
            const int off = (t + 2) * 32;
            cpa16(kds + bn * TBUF,      kgp + off);
            cpa16(kds + bn * TBUF + 16, kgp + off + 8);
            cpa16(vds + bn * TBUF,      vgp + off);
            cpa16(vds + bn * TBUF + 16, vgp + off + 8);
        }
        cpa_commit();

        const uint32_t kb = kmat + bc * TBUF;
        const uint32_t vb = vmat + bc * TBUF;

        float Sx[4][4] = {};
        #pragma unroll
        for (int c = 0; c < 4; c++) {
            uint32_t b00, b01, b10, b11;
            ldsm4t(b00, b01, b10, b11, kb + c * 16 * TPB);
            mma16(Sx[0], aQ[c], b00, b01);
            mma16(Sx[1], aQ[c], b10, b11);
            ldsm4t(b00, b01, b10, b11, kb + c * 16 * TPB + 32);
            mma16(Sx[2], aQ[c], b00, b01);
            mma16(Sx[3], aQ[c], b10, b11);
        }

        #pragma unroll
        for (int n = 0; n < 4; n++) {
            Sx[n][0] = ex2f(Sx[n][0]);
            Sx[n][1] = ex2f(Sx[n][1]);
            Sx[n][2] = ex2f(Sx[n][2]);
            Sx[n][3] = ex2f(Sx[n][3]);
        }

        #pragma unroll
        for (int kc = 0; kc < 2; kc++) {
            uint32_t aP[4];
            aP[0] = pack_bf16(Sx[2 * kc][0],     Sx[2 * kc][1]);
            aP[1] = pack_bf16(Sx[2 * kc][2],     Sx[2 * kc][3]);
            aP[2] = pack_bf16(Sx[2 * kc + 1][0], Sx[2 * kc + 1][1]);
            aP[3] = pack_bf16(Sx[2 * kc + 1][2], Sx[2 * kc + 1][3]);
            mma16(Lacc, aP, ONES_BF16X2, ONES_BF16X2);
            #pragma unroll
            for (int g = 0; g < 4; g++) {
                uint32_t v00, v01, v10, v11;
                ldsm4(v00, v01, v10, v11, vb + g * 16 * TPB + kc * 32);
                mma16(O[2 * g],     aP, v00, v01);
                mma16(O[2 * g + 1], aP, v10, v11);
            }
        }

        bc = (bc == 2) ? 0 : bc + 1;
        bn = (bn == 2) ? 0 : bn + 1;
    }

    const float inv0 = 1.f / Lacc[0], inv1 = 1.f / Lacc[2];
    #pragma unroll
    for (int dt = 0; dt < 8; dt++) {
        O[dt][0] *= inv0; O[dt][1] *= inv0;
        O[dt][2] *= inv1; O[dt][3] *= inv1;
    }

    __syncthreads();
    float* Os = reinterpret_cast<float*>(smu);   // [64 q][OP]
    #pragma unroll
    for (int dt = 0; dt < 8; dt++) {
        float* r0 = Os + (w * 16 + lq)     * OP + dt * 8 + 2 * lr;
        float* r1 = Os + (w * 16 + lq + 8) * OP + dt * 8 + 2 * lr;
        *reinterpret_cast<float2*>(r0) = make_float2(O[dt][0], O[dt][1]);
        *reinterpret_cast<float2*>(r1) = make_float2(O[dt][2], O[dt][3]);
    }
    __syncthreads();
    {
        __nv_bfloat16* Ob = out + ((size_t)b * C_ + (size_t)h * HD) * L_;
        const int d = tid >> 1, qc = (tid & 1) * 32;
        __nv_bfloat16* op = Ob + (size_t)d * L_ + q0 + qc;
        #pragma unroll
        for (int i = 0; i < 32; i += 4) {
            float4 v;
            v.x = Os[(qc + i + 0) * OP + d];
            v.y = Os[(qc + i + 1) * OP + d];
            v.z = Os[(qc + i + 2) * OP + d];
            v.w = Os[(qc + i + 3) * OP + d];
            uint2 pk;
            pk.x = pack_bf16(v.x, v.y);
            pk.y = pack_bf16(v.z, v.w);
            *reinterpret_cast<uint2*>(op + i) = pk;
        }
    }
}

// ---------------------------------------------------------------------------
extern "C" void kernel_launch(void* const* d_in, const int* in_sizes, int n_in,
                              void* d_out, int out_size) {
    const float* x      = (const float*)d_in[0];
    const float* qkv_w  = (const float*)d_in[1];
    const float* qkv_b  = (const float*)d_in[2];
    const float* proj_w = (const float*)d_in[3];
    const float* proj_b = (const float*)d_in[4];
    const float* gamma  = (const float*)d_in[5];
    const float* beta   = (const float*)d_in[6];
    float* out = (float*)d_out;

    float *xn, *part;
    __nv_bfloat16 *xnh, *qkvh, *atth, *wqh, *wph;
    cudaGetSymbolAddress((void**)&xn,   g_xn);
    cudaGetSymbolAddress((void**)&xnh,  g_xnh);
    cudaGetSymbolAddress((void**)&qkvh, g_qkvh);
    cudaGetSymbolAddress((void**)&atth, g_atth);
    cudaGetSymbolAddress((void**)&part, g_part);
    cudaGetSymbolAddress((void**)&wqh,  g_wqh);
    cudaGetSymbolAddress((void**)&wph,  g_wph);

    const int attn_smem = 6 * TBUF;   // 30720 B (>= 64*OP*4 = 18432 staging)

    gn_reduce<<<B_ * G_ * 8, 256>>>(x, part);
    gn_apply <<<B_ * G_ * 8, 256>>>(x, part, gamma, beta, xn, xnh,
                                    qkv_w, proj_w, wqh, wph);

    dim3 g_qkvgrid(L_ / 64, (3 * C_) / 128, B_);
    gemm_bf16<false, true><<<g_qkvgrid, 256>>>(wqh, qkv_b, xnh, qkvh, nullptr, 3 * C_, C_);

    dim3 g_attn(L_ / 64, NH, B_);
    attn_bf16<<<g_attn, 128, attn_smem>>>(qkvh, atth);

    dim3 g_proj(L_ / 64, C_ / 128, B_);
    gemm_bf16<true, false><<<g_proj, 256>>>(wph, proj_b, atth, out, xn, C_, C_);
}

// round 11
// speedup vs baseline: 1.1630x; 1.1630x over previous
#include <cuda_runtime.h>
#include <cuda_bf16.h>
#include <mma.h>
#include <math.h>
#include <stdint.h>

using namespace nvcuda;

#define B_   4
#define C_   256
#define L_   4096
#define G_   8
#define NH   4
#define HD   64
#define EPSV 1e-5f
#define EP   72    // gemm epilogue staging pitch (floats)
#define WP   40    // gemm W tile pitch (bf16)
#define XP   80    // gemm X tile pitch (bf16)
#define WBUF (128 * WP * 2)   // 10240 B
#define XBUF (32 * XP * 2)    //  5120 B
#define TPB  80    // attn tile row pitch (bytes)
#define TBUF (64 * TPB)       //  5120 B
#define OP   72    // attn O staging pitch (floats)
#define LOG2E 1.4426950408889634f
#define ONES_BF16X2 0x3F803F80u

// Scratch (device globals)
__device__ float         g_xn  [B_ * C_ * L_];
__device__ __nv_bfloat16 g_xnh [B_ * C_ * L_];
__device__ __nv_bfloat16 g_qkvh[B_ * 3 * C_ * L_];
__device__ __nv_bfloat16 g_atth[B_ * C_ * L_];
__device__ float         g_part[B_ * G_ * 8 * 2];
__device__ __nv_bfloat16 g_wqh [3 * C_ * C_];
__device__ __nv_bfloat16 g_wph [C_ * C_];
__device__ float         g_osp [2 * B_ * C_ * L_];    // split un-normalized O
__device__ float         g_lsp [2 * B_ * NH * L_];    // split row sums

// ---------------------------------------------------------------------------
__device__ __forceinline__ uint32_t pack_bf16(float lo, float hi) {
    __nv_bfloat162 p = __floats2bfloat162_rn(lo, hi);
    return *reinterpret_cast<uint32_t*>(&p);
}
__device__ __forceinline__ float ex2f(float x) {
    float y; asm("ex2.approx.f32 %0, %1;" : "=f"(y) : "f"(x)); return y;
}
__device__ __forceinline__ void mma16(float* d, const uint32_t* a, uint32_t b0, uint32_t b1) {
    asm volatile(
        "mma.sync.aligned.m16n8k16.row.col.f32.bf16.bf16.f32 "
        "{%0,%1,%2,%3}, {%4,%5,%6,%7}, {%8,%9}, {%0,%1,%2,%3};"
        : "+f"(d[0]), "+f"(d[1]), "+f"(d[2]), "+f"(d[3])
        : "r"(a[0]), "r"(a[1]), "r"(a[2]), "r"(a[3]), "r"(b0), "r"(b1));
}
__device__ __forceinline__ void ldsm4(uint32_t& r0, uint32_t& r1, uint32_t& r2, uint32_t& r3,
                                      uint32_t saddr) {
    asm volatile("ldmatrix.sync.aligned.m8n8.x4.shared.b16 {%0,%1,%2,%3}, [%4];"
        : "=r"(r0), "=r"(r1), "=r"(r2), "=r"(r3) : "r"(saddr));
}
__device__ __forceinline__ void ldsm4t(uint32_t& r0, uint32_t& r1, uint32_t& r2, uint32_t& r3,
                                       uint32_t saddr) {
    asm volatile("ldmatrix.sync.aligned.m8n8.x4.trans.shared.b16 {%0,%1,%2,%3}, [%4];"
        : "=r"(r0), "=r"(r1), "=r"(r2), "=r"(r3) : "r"(saddr));
}
__device__ __forceinline__ void cpa16(uint32_t dst, const void* src) {
    asm volatile("cp.async.cg.shared.global [%0], [%1], 16;" :: "r"(dst), "l"(src));
}
__device__ __forceinline__ void cpa_commit() {
    asm volatile("cp.async.commit_group;");
}
template<int N>
__device__ __forceinline__ void cpa_wait() {
    asm volatile("cp.async.wait_group %0;" :: "n"(N));
}

// ---------------------------------------------------------------------------
// GroupNorm pass 1
// ---------------------------------------------------------------------------
__global__ void gn_reduce(const float* __restrict__ x, float* __restrict__ part) {
    const int blk = blockIdx.x;
    const int bg = blk >> 3, sub = blk & 7;
    const int SL = (C_ / G_) * L_ / 8;
    const float* xp = x + (size_t)bg * (C_ / G_) * L_ + (size_t)sub * SL;

    float s = 0.f, s2 = 0.f;
    for (int i = threadIdx.x * 4; i < SL; i += blockDim.x * 4) {
        float4 v = *reinterpret_cast<const float4*>(xp + i);
        s  += v.x + v.y + v.z + v.w;
        s2 += v.x * v.x + v.y * v.y + v.z * v.z + v.w * v.w;
    }
    #pragma unroll
    for (int o = 16; o; o >>= 1) {
        s  += __shfl_xor_sync(~0u, s,  o);
        s2 += __shfl_xor_sync(~0u, s2, o);
    }
    __shared__ float rs[8], rs2[8];
    const int wid = threadIdx.x >> 5;
    if ((threadIdx.x & 31) == 0) { rs[wid] = s; rs2[wid] = s2; }
    __syncthreads();
    if (threadIdx.x == 0) {
        float ts = 0.f, ts2 = 0.f;
        #pragma unroll
        for (int i = 0; i < 8; i++) { ts += rs[i]; ts2 += rs2[i]; }
        part[blk * 2 + 0] = ts;
        part[blk * 2 + 1] = ts2;
    }
}

// ---------------------------------------------------------------------------
// GroupNorm pass 2: fp32 xn + bf16 xnh; ALSO converts weights to bf16
// ---------------------------------------------------------------------------
__global__ void gn_apply(const float* __restrict__ x,
                         const float* __restrict__ part,
                         const float* __restrict__ gamma,
                         const float* __restrict__ beta,
                         float* __restrict__ xn,
                         __nv_bfloat16* __restrict__ xnh,
                         const float* __restrict__ qkv_w,
                         const float* __restrict__ proj_w,
                         __nv_bfloat16* __restrict__ wqh,
                         __nv_bfloat16* __restrict__ wph) {
    const int blk = blockIdx.x;
    const int bg = blk >> 3, sub = blk & 7;
    const int g = bg & (G_ - 1);
    const int SL = (C_ / G_) * L_ / 8;
    const int n = (C_ / G_) * L_;

    // fused weight conversion (256 blk x 256 thr x 4 = 262144 = 4*C*C)
    {
        const int wi = (blk * 256 + threadIdx.x) * 4;
        const float* src; __nv_bfloat16* dst; int off;
        if (wi < 3 * C_ * C_) { src = qkv_w; dst = wqh; off = wi; }
        else                  { src = proj_w; dst = wph; off = wi - 3 * C_ * C_; }
        float4 v = *reinterpret_cast<const float4*>(src + off);
        uint2 pk;
        pk.x = pack_bf16(v.x, v.y);
        pk.y = pack_bf16(v.z, v.w);
        *reinterpret_cast<uint2*>(dst + off) = pk;
    }

    float ts = 0.f, ts2 = 0.f;
    #pragma unroll
    for (int i = 0; i < 8; i++) {
        ts  += part[(bg * 8 + i) * 2 + 0];
        ts2 += part[(bg * 8 + i) * 2 + 1];
    }
    const float mean = ts / (float)n;
    const float inv  = rsqrtf(ts2 / (float)n - mean * mean + EPSV);

    const size_t base = (size_t)bg * (C_ / G_) * L_ + (size_t)sub * SL;
    const float* xp = x + base;
    float* yp = xn + base;
    __nv_bfloat16* hp = xnh + base;
    const int off0 = sub * SL;
    for (int i = threadIdx.x * 4; i < SL; i += blockDim.x * 4) {
        const int c = g * (C_ / G_) + ((off0 + i) >> 12);
        const float ga = gamma[c], be = beta[c];
        float4 v = *reinterpret_cast<const float4*>(xp + i);
        float4 o;
        o.x = (v.x - mean) * inv * ga + be;
        o.y = (v.y - mean) * inv * ga + be;
        o.z = (v.z - mean) * inv * ga + be;
        o.w = (v.w - mean) * inv * ga + be;
        *reinterpret_cast<float4*>(yp + i) = o;
        uint2 pk;
        pk.x = pack_bf16(o.x, o.y);
        pk.y = pack_bf16(o.z, o.w);
        *reinterpret_cast<uint2*>(hp + i) = pk;
    }
}

// ---------------------------------------------------------------------------
// bf16 wmma GEMM: 128m x 64n tile, 3-stage cp.async pipeline, 256 threads.
// ---------------------------------------------------------------------------
template<bool RESID, bool QKVOUT>
__global__ __launch_bounds__(256)
void gemm_bf16(const __nv_bfloat16* __restrict__ Wh,
               const float* __restrict__ bias,
               const __nv_bfloat16* __restrict__ X,
               void* __restrict__ Yv,
               const float* __restrict__ R,
               int Mtot, int KDIM) {
    const int n0 = blockIdx.x * 64;
    const int m0 = blockIdx.y * 128;
    const int b  = blockIdx.z;
    const __nv_bfloat16* Xb = X + (size_t)b * KDIM * L_;

    __shared__ uint8_t smraw[3 * (WBUF + XBUF)];
    const uint32_t sb = (uint32_t)__cvta_generic_to_shared(smraw);

    const int tid = threadIdx.x;
    const int wid = tid >> 5;
    const int wm = wid >> 1, wn = wid & 1;

    const int wr0 = tid >> 1, wk0 = (tid & 1) * 16;
    const int xr  = tid >> 3, xn8 = (tid & 7) * 8;

    const int NS = KDIM / 32;

    auto issue = [&](int s) {
        const int k0 = s * 32;
        const uint32_t wbase = sb + (s % 3) * WBUF;
        const uint32_t xbase = sb + 3 * WBUF + (s % 3) * XBUF;
        cpa16(wbase + (wr0 * WP + wk0) * 2,
              Wh + (size_t)(m0 + wr0) * KDIM + k0 + wk0);
        cpa16(wbase + (wr0 * WP + wk0 + 8) * 2,
              Wh + (size_t)(m0 + wr0) * KDIM + k0 + wk0 + 8);
        cpa16(xbase + (xr * XP + xn8) * 2,
              Xb + (size_t)(k0 + xr) * L_ + n0 + xn8);
    };

    wmma::fragment<wmma::accumulator, 16, 16, 16, float> c00, c01, c10, c11;
    wmma::fill_fragment(c00, 0.f); wmma::fill_fragment(c01, 0.f);
    wmma::fill_fragment(c10, 0.f); wmma::fill_fragment(c11, 0.f);

    issue(0); cpa_commit();
    issue(1); cpa_commit();

    for (int s = 0; s < NS; s++) {
        cpa_wait<1>();
        __syncthreads();
        if (s + 2 < NS) issue(s + 2);
        cpa_commit();

        const __nv_bfloat16* Ws = reinterpret_cast<const __nv_bfloat16*>(smraw + (s % 3) * WBUF);
        const __nv_bfloat16* Xs = reinterpret_cast<const __nv_bfloat16*>(smraw + 3 * WBUF + (s % 3) * XBUF);
        #pragma unroll
        for (int ks = 0; ks < 32; ks += 16) {
            wmma::fragment<wmma::matrix_a, 16, 16, 16, __nv_bfloat16, wmma::row_major> a0, a1;
            wmma::fragment<wmma::matrix_b, 16, 16, 16, __nv_bfloat16, wmma::row_major> b0, b1;
            wmma::load_matrix_sync(a0, &Ws[(wm * 32) * WP + ks], WP);
            wmma::load_matrix_sync(a1, &Ws[(wm * 32 + 16) * WP + ks], WP);
            wmma::load_matrix_sync(b0, &Xs[ks * XP + wn * 32], XP);
            wmma::load_matrix_sync(b1, &Xs[ks * XP + wn * 32 + 16], XP);
            wmma::mma_sync(c00, a0, b0, c00);
            wmma::mma_sync(c01, a0, b1, c01);
            wmma::mma_sync(c10, a1, b0, c10);
            wmma::mma_sync(c11, a1, b1, c11);
        }
    }
    __syncthreads();

    float* smf = reinterpret_cast<float*>(smraw);
    wmma::store_matrix_sync(&smf[(wm * 32)      * EP + wn * 32],      c00, EP, wmma::mem_row_major);
    wmma::store_matrix_sync(&smf[(wm * 32)      * EP + wn * 32 + 16], c01, EP, wmma::mem_row_major);
    wmma::store_matrix_sync(&smf[(wm * 32 + 16) * EP + wn * 32],      c10, EP, wmma::mem_row_major);
    wmma::store_matrix_sync(&smf[(wm * 32 + 16) * EP + wn * 32 + 16], c11, EP, wmma::mem_row_major);
    __syncthreads();
    {
        const int m = tid >> 1, nn = (tid & 1) * 32;
        const float bv = bias[m0 + m];
        const size_t orow = (size_t)(m0 + m) * L_ + n0 + nn;
        if (QKVOUT) {
            __nv_bfloat16* Ybh = (__nv_bfloat16*)Yv + (size_t)b * Mtot * L_;
            const float sc = (m0 + m < C_) ? 0.125f * LOG2E : 1.0f;
            #pragma unroll
            for (int i = 0; i < 32; i += 4) {
                float4 v = *reinterpret_cast<const float4*>(&smf[m * EP + nn + i]);
                v.x = (v.x + bv) * sc; v.y = (v.y + bv) * sc;
                v.z = (v.z + bv) * sc; v.w = (v.w + bv) * sc;
                uint2 pk;
                pk.x = pack_bf16(v.x, v.y);
                pk.y = pack_bf16(v.z, v.w);
                *reinterpret_cast<uint2*>(Ybh + orow + i) = pk;
            }
        } else {
            float* Yb = (float*)Yv + (size_t)b * Mtot * L_;
            #pragma unroll
            for (int i = 0; i < 32; i += 4) {
                float4 v = *reinterpret_cast<const float4*>(&smf[m * EP + nn + i]);
                v.x += bv; v.y += bv; v.z += bv; v.w += bv;
                if (RESID) {
                    float4 r = *reinterpret_cast<const float4*>(&R[(size_t)b * Mtot * L_ + orow + i]);
                    v.x += r.x; v.y += r.y; v.z += r.z; v.w += r.w;
                }
                *reinterpret_cast<float4*>(Yb + orow + i) = v;
            }
        }
    }
}

// ---------------------------------------------------------------------------
// Flash attention, split-K: 128-query CTAs (256 thr, occ 3), each CTA does
// HALF the keys (2048). exp-no-max => un-normalized O and l are additive
// across splits. Writes fp32 O_unnorm + l to scratch; combine kernel merges.
// ---------------------------------------------------------------------------
__global__ __launch_bounds__(256, 3)
void attn_split(const __nv_bfloat16* __restrict__ qkv,
                float* __restrict__ osp, float* __restrict__ lsp) {
    const int q0 = blockIdx.x * 128;
    const int h  = blockIdx.y;
    const int bz = blockIdx.z;
    const int b  = bz >> 1, sp = bz & 1;
    const int k00 = sp * (L_ / 2);
    const int NT  = (L_ / 2) / 32;   // 64 tiles

    extern __shared__ uint32_t smu[];
    const uint32_t sbase = (uint32_t)__cvta_generic_to_shared(smu);

    const int tid  = threadIdx.x;
    const int lane = tid & 31;
    const int w    = tid >> 5;
    const int lq   = lane >> 2;
    const int lr   = lane & 3;

    const size_t base = ((size_t)b * 3 * C_ + (size_t)h * HD) * L_;
    const uint16_t* Qp = (const uint16_t*)qkv + base;
    const uint16_t* Kp = Qp + (size_t)C_ * L_;
    const uint16_t* Vp = Qp + (size_t)2 * C_ * L_;

    uint32_t aQ[4][4];
    {
        const int qw = q0 + w * 16;
        #pragma unroll
        for (int c = 0; c < 4; c++) {
            const int d0 = c * 16 + 2 * lr;
            const uint16_t* qb = Qp + (size_t)d0 * L_ + qw;
            aQ[c][0] = (uint32_t)qb[lq]     | ((uint32_t)qb[(size_t)L_ + lq])     << 16;
            aQ[c][1] = (uint32_t)qb[lq + 8] | ((uint32_t)qb[(size_t)L_ + lq + 8]) << 16;
            const uint16_t* qc = qb + (size_t)8 * L_;
            aQ[c][2] = (uint32_t)qc[lq]     | ((uint32_t)qc[(size_t)L_ + lq])     << 16;
            aQ[c][3] = (uint32_t)qc[lq + 8] | ((uint32_t)qc[(size_t)L_ + lq + 8]) << 16;
        }
    }

    // loaders: 256 threads, one 16B chunk each per buffer per tile
    const int ld_d = tid >> 2;
    const int ld_c = (tid & 3);
    const uint16_t* kgp = Kp + (size_t)ld_d * L_ + k00 + ld_c * 8;
    const uint16_t* vgp = Vp + (size_t)ld_d * L_ + k00 + ld_c * 8;
    const uint32_t kds = sbase + ld_d * TPB + ld_c * 16;
    const uint32_t vds = sbase + 3 * TBUF + ld_d * TPB + ld_c * 16;

    const int mi = lane >> 3;
    const int r8 = lane & 7;
    const uint32_t kmat = sbase + ((mi & 1) * 8 + r8) * TPB + (mi >> 1) * 16;
    const uint32_t vmat = sbase + 3 * TBUF + ((mi >> 1) * 8 + r8) * TPB + (mi & 1) * 16;

    cpa16(kds,        kgp);       cpa16(vds,        vgp);       cpa_commit();
    cpa16(kds + TBUF, kgp + 32);  cpa16(vds + TBUF, vgp + 32);  cpa_commit();

    float O[8][4] = {};
    float Lacc[4] = {};
    int bc = 0, bn = 2;

    for (int t = 0; t < NT; t++) {
        cpa_wait<1>();
        __syncthreads();

        if (t < NT - 2) {
            const int off = (t + 2) * 32;
            cpa16(kds + bn * TBUF, kgp + off);
            cpa16(vds + bn * TBUF, vgp + off);
        }
        cpa_commit();

        const uint32_t kb = kmat + bc * TBUF;
        const uint32_t vb = vmat + bc * TBUF;

        float Sx[4][4] = {};
        #pragma unroll
        for (int c = 0; c < 4; c++) {
            uint32_t b00, b01, b10, b11;
            ldsm4t(b00, b01, b10, b11, kb + c * 16 * TPB);
            mma16(Sx[0], aQ[c], b00, b01);
            mma16(Sx[1], aQ[c], b10, b11);
            ldsm4t(b00, b01, b10, b11, kb + c * 16 * TPB + 32);
            mma16(Sx[2], aQ[c], b00, b01);
            mma16(Sx[3], aQ[c], b10, b11);
        }

        #pragma unroll
        for (int n = 0; n < 4; n++) {
            Sx[n][0] = ex2f(Sx[n][0]);
            Sx[n][1] = ex2f(Sx[n][1]);
            Sx[n][2] = ex2f(Sx[n][2]);
            Sx[n][3] = ex2f(Sx[n][3]);
        }

        #pragma unroll
        for (int kc = 0; kc < 2; kc++) {
            uint32_t aP[4];
            aP[0] = pack_bf16(Sx[2 * kc][0],     Sx[2 * kc][1]);
            aP[1] = pack_bf16(Sx[2 * kc][2],     Sx[2 * kc][3]);
            aP[2] = pack_bf16(Sx[2 * kc + 1][0], Sx[2 * kc + 1][1]);
            aP[3] = pack_bf16(Sx[2 * kc + 1][2], Sx[2 * kc + 1][3]);
            mma16(Lacc, aP, ONES_BF16X2, ONES_BF16X2);
            #pragma unroll
            for (int g = 0; g < 4; g++) {
                uint32_t v00, v01, v10, v11;
                ldsm4(v00, v01, v10, v11, vb + g * 16 * TPB + kc * 32);
                mma16(O[2 * g],     aP, v00, v01);
                mma16(O[2 * g + 1], aP, v10, v11);
            }
        }

        bc = (bc == 2) ? 0 : bc + 1;
        bn = (bn == 2) ? 0 : bn + 1;
    }

    // publish row sums (all 4 lr lanes hold identical values; lr==0 writes)
    if (lr == 0) {
        float* lp = lsp + ((size_t)(sp * B_ + b) * NH + h) * L_ + q0 + w * 16;
        lp[lq]     = Lacc[0];
        lp[lq + 8] = Lacc[2];
    }

    // stage un-normalized O, write fp32 transposed
    __syncthreads();
    float* Os = reinterpret_cast<float*>(smu);   // [128 q][OP]
    #pragma unroll
    for (int dt = 0; dt < 8; dt++) {
        float* r0 = Os + (w * 16 + lq)     * OP + dt * 8 + 2 * lr;
        float* r1 = Os + (w * 16 + lq + 8) * OP + dt * 8 + 2 * lr;
        *reinterpret_cast<float2*>(r0) = make_float2(O[dt][0], O[dt][1]);
        *reinterpret_cast<float2*>(r1) = make_float2(O[dt][2], O[dt][3]);
    }
    __syncthreads();
    {
        float* Ob = osp + ((size_t)(sp * B_ + b) * C_ + (size_t)h * HD) * L_;
        const int d = tid >> 2, qc = (tid & 3) * 32;
        float* op = Ob + (size_t)d * L_ + q0 + qc;
        #pragma unroll
        for (int i = 0; i < 32; i += 4) {
            float4 v;
            v.x = Os[(qc + i + 0) * OP + d];
            v.y = Os[(qc + i + 1) * OP + d];
            v.z = Os[(qc + i + 2) * OP + d];
            v.w = Os[(qc + i + 3) * OP + d];
            *reinterpret_cast<float4*>(op + i) = v;
        }
    }
}

// ---------------------------------------------------------------------------
// Combine: atth = (O0 + O1) / (l0 + l1), bf16 out. 8 elems per thread.
// ---------------------------------------------------------------------------
__global__ void attn_combine(const float* __restrict__ osp,
                             const float* __restrict__ lsp,
                             __nv_bfloat16* __restrict__ atth) {
    const uint32_t base = (blockIdx.x * 256 + threadIdx.x) * 8;
    const int l_idx = base & (L_ - 1);
    const int bcg = base >> 12;
    const int c = bcg & (C_ - 1);
    const int b = bcg >> 8;
    const int h = c >> 6;

    const float* o0 = osp + base;
    const float* o1 = osp + (size_t)B_ * C_ * L_ + base;
    const float* l0 = lsp + ((size_t)b * NH + h) * L_ + l_idx;
    const float* l1 = l0 + (size_t)B_ * NH * L_;

    float4 a0 = *reinterpret_cast<const float4*>(o0);
    float4 a1 = *reinterpret_cast<const float4*>(o0 + 4);
    float4 b0 = *reinterpret_cast<const float4*>(o1);
    float4 b1 = *reinterpret_cast<const float4*>(o1 + 4);
    float4 s0 = *reinterpret_cast<const float4*>(l0);
    float4 s1 = *reinterpret_cast<const float4*>(l0 + 4);
    float4 t0 = *reinterpret_cast<const float4*>(l1);
    float4 t1 = *reinterpret_cast<const float4*>(l1 + 4);

    float r[8];
    r[0] = (a0.x + b0.x) / (s0.x + t0.x);
    r[1] = (a0.y + b0.y) / (s0.y + t0.y);
    r[2] = (a0.z + b0.z) / (s0.z + t0.z);
    r[3] = (a0.w + b0.w) / (s0.w + t0.w);
    r[4] = (a1.x + b1.x) / (s1.x + t1.x);
    r[5] = (a1.y + b1.y) / (s1.y + t1.y);
    r[6] = (a1.z + b1.z) / (s1.z + t1.z);
    r[7] = (a1.w + b1.w) / (s1.w + t1.w);

    uint4 pk;
    pk.x = pack_bf16(r[0], r[1]);
    pk.y = pack_bf16(r[2], r[3]);
    pk.z = pack_bf16(r[4], r[5]);
    pk.w = pack_bf16(r[6], r[7]);
    *reinterpret_cast<uint4*>(atth + base) = pk;
}

// ---------------------------------------------------------------------------
extern "C" void kernel_launch(void* const* d_in, const int* in_sizes, int n_in,
                              void* d_out, int out_size) {
    const float* x      = (const float*)d_in[0];
    const float* qkv_w  = (const float*)d_in[1];
    const float* qkv_b  = (const float*)d_in[2];
    const float* proj_w = (const float*)d_in[3];
    const float* proj_b = (const float*)d_in[4];
    const float* gamma  = (const float*)d_in[5];
    const float* beta   = (const float*)d_in[6];
    float* out = (float*)d_out;

    float *xn, *part, *osp, *lsp;
    __nv_bfloat16 *xnh, *qkvh, *atth, *wqh, *wph;
    cudaGetSymbolAddress((void**)&xn,   g_xn);
    cudaGetSymbolAddress((void**)&xnh,  g_xnh);
    cudaGetSymbolAddress((void**)&qkvh, g_qkvh);
    cudaGetSymbolAddress((void**)&atth, g_atth);
    cudaGetSymbolAddress((void**)&part, g_part);
    cudaGetSymbolAddress((void**)&wqh,  g_wqh);
    cudaGetSymbolAddress((void**)&wph,  g_wph);
    cudaGetSymbolAddress((void**)&osp,  g_osp);
    cudaGetSymbolAddress((void**)&lsp,  g_lsp);

    const int attn_smem = 128 * OP * (int)sizeof(float);   // 36864 B >= 6*TBUF

    gn_reduce<<<B_ * G_ * 8, 256>>>(x, part);
    gn_apply <<<B_ * G_ * 8, 256>>>(x, part, gamma, beta, xn, xnh,
                                    qkv_w, proj_w, wqh, wph);

    dim3 g_qkvgrid(L_ / 64, (3 * C_) / 128, B_);
    gemm_bf16<false, true><<<g_qkvgrid, 256>>>(wqh, qkv_b, xnh, qkvh, nullptr, 3 * C_, C_);

    dim3 g_attn(L_ / 128, NH, B_ * 2);
    attn_split<<<g_attn, 256, attn_smem>>>(qkvh, osp, lsp);

    attn_combine<<<(B_ * C_ * L_) / (256 * 8), 256>>>(osp, lsp, atth);

    dim3 g_proj(L_ / 64, C_ / 128, B_);
    gemm_bf16<true, false><<<g_proj, 256>>>(wph, proj_b, atth, out, xn, C_, C_);
}

// round 12
// speedup vs baseline: 1.1656x; 1.0022x over previous
#include <cuda_runtime.h>
#include <cuda_bf16.h>
#include <cuda_fp16.h>
#include <mma.h>
#include <math.h>
#include <stdint.h>

using namespace nvcuda;

#define B_   4
#define C_   256
#define L_   4096
#define G_   8
#define NH   4
#define HD   64
#define EPSV 1e-5f
#define EP   72    // gemm epilogue staging pitch (floats)
#define WP   40    // gemm W tile pitch (bf16)
#define XP   80    // gemm X tile pitch (bf16)
#define WBUF (128 * WP * 2)   // 10240 B
#define XBUF (32 * XP * 2)    //  5120 B
#define TPB  80    // attn tile row pitch (bytes)
#define TBUF (64 * TPB)       //  5120 B
#define OP   72    // attn O staging pitch (floats)
#define LOG2E 1.4426950408889634f
#define ONES_F16X2 0x3C003C00u

// Scratch (device globals)
__device__ float         g_xn  [B_ * C_ * L_];
__device__ __nv_bfloat16 g_xnh [B_ * C_ * L_];
__device__ __nv_bfloat16 g_qkvh[B_ * 3 * C_ * L_];   // Q,K bf16; V region holds fp16
__device__ __nv_bfloat16 g_atth[B_ * C_ * L_];
__device__ float         g_part[B_ * G_ * 8 * 2];
__device__ __nv_bfloat16 g_wqh [3 * C_ * C_];
__device__ __nv_bfloat16 g_wph [C_ * C_];
__device__ __nv_bfloat16 g_osp [2 * B_ * C_ * L_];   // split un-normalized O (bf16)
__device__ float         g_lsp [2 * B_ * NH * L_];   // split row sums

// ---------------------------------------------------------------------------
__device__ __forceinline__ uint32_t pack_bf16(float lo, float hi) {
    __nv_bfloat162 p = __floats2bfloat162_rn(lo, hi);
    return *reinterpret_cast<uint32_t*>(&p);
}
__device__ __forceinline__ uint32_t pack_f16(float lo, float hi) {
    __half2 p = __floats2half2_rn(lo, hi);
    return *reinterpret_cast<uint32_t*>(&p);
}
// 2^lo, 2^hi computed in f16, returned packed (lo in low half)
__device__ __forceinline__ uint32_t exp2_f16x2(float lo, float hi) {
    uint32_t p, r;
    asm("cvt.rn.f16x2.f32 %0, %1, %2;" : "=r"(p) : "f"(hi), "f"(lo));
    asm("ex2.approx.f16x2 %0, %1;" : "=r"(r) : "r"(p));
    return r;
}
__device__ __forceinline__ float bf_lo(uint32_t u) { return __uint_as_float(u << 16); }
__device__ __forceinline__ float bf_hi(uint32_t u) { return __uint_as_float(u & 0xFFFF0000u); }
// bf16 MMA
__device__ __forceinline__ void mma16(float* d, const uint32_t* a, uint32_t b0, uint32_t b1) {
    asm volatile(
        "mma.sync.aligned.m16n8k16.row.col.f32.bf16.bf16.f32 "
        "{%0,%1,%2,%3}, {%4,%5,%6,%7}, {%8,%9}, {%0,%1,%2,%3};"
        : "+f"(d[0]), "+f"(d[1]), "+f"(d[2]), "+f"(d[3])
        : "r"(a[0]), "r"(a[1]), "r"(a[2]), "r"(a[3]), "r"(b0), "r"(b1));
}
// fp16 MMA (P @ V path)
__device__ __forceinline__ void mma16h(float* d, const uint32_t* a, uint32_t b0, uint32_t b1) {
    asm volatile(
        "mma.sync.aligned.m16n8k16.row.col.f32.f16.f16.f32 "
        "{%0,%1,%2,%3}, {%4,%5,%6,%7}, {%8,%9}, {%0,%1,%2,%3};"
        : "+f"(d[0]), "+f"(d[1]), "+f"(d[2]), "+f"(d[3])
        : "r"(a[0]), "r"(a[1]), "r"(a[2]), "r"(a[3]), "r"(b0), "r"(b1));
}
__device__ __forceinline__ void ldsm4(uint32_t& r0, uint32_t& r1, uint32_t& r2, uint32_t& r3,
                                      uint32_t saddr) {
    asm volatile("ldmatrix.sync.aligned.m8n8.x4.shared.b16 {%0,%1,%2,%3}, [%4];"
        : "=r"(r0), "=r"(r1), "=r"(r2), "=r"(r3) : "r"(saddr));
}
__device__ __forceinline__ void ldsm4t(uint32_t& r0, uint32_t& r1, uint32_t& r2, uint32_t& r3,
                                       uint32_t saddr) {
    asm volatile("ldmatrix.sync.aligned.m8n8.x4.trans.shared.b16 {%0,%1,%2,%3}, [%4];"
        : "=r"(r0), "=r"(r1), "=r"(r2), "=r"(r3) : "r"(saddr));
}
__device__ __forceinline__ void cpa16(uint32_t dst, const void* src) {
    asm volatile("cp.async.cg.shared.global [%0], [%1], 16;" :: "r"(dst), "l"(src));
}
__device__ __forceinline__ void cpa_commit() {
    asm volatile("cp.async.commit_group;");
}
template<int N>
__device__ __forceinline__ void cpa_wait() {
    asm volatile("cp.async.wait_group %0;" :: "n"(N));
}

// ---------------------------------------------------------------------------
// GroupNorm pass 1
// ---------------------------------------------------------------------------
__global__ void gn_reduce(const float* __restrict__ x, float* __restrict__ part) {
    const int blk = blockIdx.x;
    const int bg = blk >> 3, sub = blk & 7;
    const int SL = (C_ / G_) * L_ / 8;
    const float* xp = x + (size_t)bg * (C_ / G_) * L_ + (size_t)sub * SL;

    float s = 0.f, s2 = 0.f;
    for (int i = threadIdx.x * 4; i < SL; i += blockDim.x * 4) {
        float4 v = *reinterpret_cast<const float4*>(xp + i);
        s  += v.x + v.y + v.z + v.w;
        s2 += v.x * v.x + v.y * v.y + v.z * v.z + v.w * v.w;
    }
    #pragma unroll
    for (int o = 16; o; o >>= 1) {
        s  += __shfl_xor_sync(~0u, s,  o);
        s2 += __shfl_xor_sync(~0u, s2, o);
    }
    __shared__ float rs[8], rs2[8];
    const int wid = threadIdx.x >> 5;
    if ((threadIdx.x & 31) == 0) { rs[wid] = s; rs2[wid] = s2; }
    __syncthreads();
    if (threadIdx.x == 0) {
        float ts = 0.f, ts2 = 0.f;
        #pragma unroll
        for (int i = 0; i < 8; i++) { ts += rs[i]; ts2 += rs2[i]; }
        part[blk * 2 + 0] = ts;
        part[blk * 2 + 1] = ts2;
    }
}

// ---------------------------------------------------------------------------
// GroupNorm pass 2: fp32 xn + bf16 xnh; ALSO converts weights to bf16
// ---------------------------------------------------------------------------
__global__ void gn_apply(const float* __restrict__ x,
                         const float* __restrict__ part,
                         const float* __restrict__ gamma,
                         const float* __restrict__ beta,
                         float* __restrict__ xn,
                         __nv_bfloat16* __restrict__ xnh,
                         const float* __restrict__ qkv_w,
                         const float* __restrict__ proj_w,
                         __nv_bfloat16* __restrict__ wqh,
                         __nv_bfloat16* __restrict__ wph) {
    const int blk = blockIdx.x;
    const int bg = blk >> 3, sub = blk & 7;
    const int g = bg & (G_ - 1);
    const int SL = (C_ / G_) * L_ / 8;
    const int n = (C_ / G_) * L_;

    {
        const int wi = (blk * 256 + threadIdx.x) * 4;
        const float* src; __nv_bfloat16* dst; int off;
        if (wi < 3 * C_ * C_) { src = qkv_w; dst = wqh; off = wi; }
        else                  { src = proj_w; dst = wph; off = wi - 3 * C_ * C_; }
        float4 v = *reinterpret_cast<const float4*>(src + off);
        uint2 pk;
        pk.x = pack_bf16(v.x, v.y);
        pk.y = pack_bf16(v.z, v.w);
        *reinterpret_cast<uint2*>(dst + off) = pk;
    }

    float ts = 0.f, ts2 = 0.f;
    #pragma unroll
    for (int i = 0; i < 8; i++) {
        ts  += part[(bg * 8 + i) * 2 + 0];
        ts2 += part[(bg * 8 + i) * 2 + 1];
    }
    const float mean = ts / (float)n;
    const float inv  = rsqrtf(ts2 / (float)n - mean * mean + EPSV);

    const size_t base = (size_t)bg * (C_ / G_) * L_ + (size_t)sub * SL;
    const float* xp = x + base;
    float* yp = xn + base;
    __nv_bfloat16* hp = xnh + base;
    const int off0 = sub * SL;
    for (int i = threadIdx.x * 4; i < SL; i += blockDim.x * 4) {
        const int c = g * (C_ / G_) + ((off0 + i) >> 12);
        const float ga = gamma[c], be = beta[c];
        float4 v = *reinterpret_cast<const float4*>(xp + i);
        float4 o;
        o.x = (v.x - mean) * inv * ga + be;
        o.y = (v.y - mean) * inv * ga + be;
        o.z = (v.z - mean) * inv * ga + be;
        o.w = (v.w - mean) * inv * ga + be;
        *reinterpret_cast<float4*>(yp + i) = o;
        uint2 pk;
        pk.x = pack_bf16(o.x, o.y);
        pk.y = pack_bf16(o.z, o.w);
        *reinterpret_cast<uint2*>(hp + i) = pk;
    }
}

// ---------------------------------------------------------------------------
// bf16 wmma GEMM: 128m x 64n tile, 3-stage cp.async pipeline, 256 threads.
// QKVOUT: Q rows scaled by 0.125*log2e (bf16), K rows bf16, V rows fp16.
// ---------------------------------------------------------------------------
template<bool RESID, bool QKVOUT>
__global__ __launch_bounds__(256)
void gemm_bf16(const __nv_bfloat16* __restrict__ Wh,
               const float* __restrict__ bias,
               const __nv_bfloat16* __restrict__ X,
               void* __restrict__ Yv,
               const float* __restrict__ R,
               int Mtot, int KDIM) {
    const int n0 = blockIdx.x * 64;
    const int m0 = blockIdx.y * 128;
    const int b  = blockIdx.z;
    const __nv_bfloat16* Xb = X + (size_t)b * KDIM * L_;

    __shared__ uint8_t smraw[3 * (WBUF + XBUF)];
    const uint32_t sb = (uint32_t)__cvta_generic_to_shared(smraw);

    const int tid = threadIdx.x;
    const int wid = tid >> 5;
    const int wm = wid >> 1, wn = wid & 1;

    const int wr0 = tid >> 1, wk0 = (tid & 1) * 16;
    const int xr  = tid >> 3, xn8 = (tid & 7) * 8;

    const int NS = KDIM / 32;

    auto issue = [&](int s) {
        const int k0 = s * 32;
        const uint32_t wbase = sb + (s % 3) * WBUF;
        const uint32_t xbase = sb + 3 * WBUF + (s % 3) * XBUF;
        cpa16(wbase + (wr0 * WP + wk0) * 2,
              Wh + (size_t)(m0 + wr0) * KDIM + k0 + wk0);
        cpa16(wbase + (wr0 * WP + wk0 + 8) * 2,
              Wh + (size_t)(m0 + wr0) * KDIM + k0 + wk0 + 8);
        cpa16(xbase + (xr * XP + xn8) * 2,
              Xb + (size_t)(k0 + xr) * L_ + n0 + xn8);
    };

    wmma::fragment<wmma::accumulator, 16, 16, 16, float> c00, c01, c10, c11;
    wmma::fill_fragment(c00, 0.f); wmma::fill_fragment(c01, 0.f);
    wmma::fill_fragment(c10, 0.f); wmma::fill_fragment(c11, 0.f);

    issue(0); cpa_commit();
    issue(1); cpa_commit();

    for (int s = 0; s < NS; s++) {
        cpa_wait<1>();
        __syncthreads();
        if (s + 2 < NS) issue(s + 2);
        cpa_commit();

        const __nv_bfloat16* Ws = reinterpret_cast<const __nv_bfloat16*>(smraw + (s % 3) * WBUF);
        const __nv_bfloat16* Xs = reinterpret_cast<const __nv_bfloat16*>(smraw + 3 * WBUF + (s % 3) * XBUF);
        #pragma unroll
        for (int ks = 0; ks < 32; ks += 16) {
            wmma::fragment<wmma::matrix_a, 16, 16, 16, __nv_bfloat16, wmma::row_major> a0, a1;
            wmma::fragment<wmma::matrix_b, 16, 16, 16, __nv_bfloat16, wmma::row_major> b0, b1;
            wmma::load_matrix_sync(a0, &Ws[(wm * 32) * WP + ks], WP);
            wmma::load_matrix_sync(a1, &Ws[(wm * 32 + 16) * WP + ks], WP);
            wmma::load_matrix_sync(b0, &Xs[ks * XP + wn * 32], XP);
            wmma::load_matrix_sync(b1, &Xs[ks * XP + wn * 32 + 16], XP);
            wmma::mma_sync(c00, a0, b0, c00);
            wmma::mma_sync(c01, a0, b1, c01);
            wmma::mma_sync(c10, a1, b0, c10);
            wmma::mma_sync(c11, a1, b1, c11);
        }
    }
    __syncthreads();

    float* smf = reinterpret_cast<float*>(smraw);
    wmma::store_matrix_sync(&smf[(wm * 32)      * EP + wn * 32],      c00, EP, wmma::mem_row_major);
    wmma::store_matrix_sync(&smf[(wm * 32)      * EP + wn * 32 + 16], c01, EP, wmma::mem_row_major);
    wmma::store_matrix_sync(&smf[(wm * 32 + 16) * EP + wn * 32],      c10, EP, wmma::mem_row_major);
    wmma::store_matrix_sync(&smf[(wm * 32 + 16) * EP + wn * 32 + 16], c11, EP, wmma::mem_row_major);
    __syncthreads();
    {
        const int m = tid >> 1, nn = (tid & 1) * 32;
        const float bv = bias[m0 + m];
        const size_t orow = (size_t)(m0 + m) * L_ + n0 + nn;
        if (QKVOUT) {
            __nv_bfloat16* Ybh = (__nv_bfloat16*)Yv + (size_t)b * Mtot * L_;
            const bool isQ = (m0 + m < C_);
            const bool isV = (m0 + m >= 2 * C_);
            const float sc = isQ ? 0.125f * LOG2E : 1.0f;
            #pragma unroll
            for (int i = 0; i < 32; i += 4) {
                float4 v = *reinterpret_cast<const float4*>(&smf[m * EP + nn + i]);
                v.x = (v.x + bv) * sc; v.y = (v.y + bv) * sc;
                v.z = (v.z + bv) * sc; v.w = (v.w + bv) * sc;
                uint2 pk;
                if (isV) {           // V rows stored fp16 for the f16 PV MMA
                    pk.x = pack_f16(v.x, v.y);
                    pk.y = pack_f16(v.z, v.w);
                } else {
                    pk.x = pack_bf16(v.x, v.y);
                    pk.y = pack_bf16(v.z, v.w);
                }
                *reinterpret_cast<uint2*>(Ybh + orow + i) = pk;
            }
        } else {
            float* Yb = (float*)Yv + (size_t)b * Mtot * L_;
            #pragma unroll
            for (int i = 0; i < 32; i += 4) {
                float4 v = *reinterpret_cast<const float4*>(&smf[m * EP + nn + i]);
                v.x += bv; v.y += bv; v.z += bv; v.w += bv;
                if (RESID) {
                    float4 r = *reinterpret_cast<const float4*>(&R[(size_t)b * Mtot * L_ + orow + i]);
                    v.x += r.x; v.y += r.y; v.z += r.z; v.w += r.w;
                }
                *reinterpret_cast<float4*>(Yb + orow + i) = v;
            }
        }
    }
}

// ---------------------------------------------------------------------------
// Flash attention split-K (KSPLIT=2), 128q CTAs, 256 thr, occ 3.
// S via bf16 MMA; P = 2^S computed in f16x2 (half the MUFU work, packs free);
// PV + row-sum MMAs in fp16. Writes bf16 O_unnorm + fp32 l.
// ---------------------------------------------------------------------------
__global__ __launch_bounds__(256, 3)
void attn_split(const __nv_bfloat16* __restrict__ qkv,
                __nv_bfloat16* __restrict__ osp, float* __restrict__ lsp) {
    const int q0 = blockIdx.x * 128;
    const int h  = blockIdx.y;
    const int bz = blockIdx.z;
    const int b  = bz >> 1, sp = bz & 1;
    const int k00 = sp * (L_ / 2);
    const int NT  = (L_ / 2) / 32;   // 64 tiles

    extern __shared__ uint32_t smu[];
    const uint32_t sbase = (uint32_t)__cvta_generic_to_shared(smu);

    const int tid  = threadIdx.x;
    const int lane = tid & 31;
    const int w    = tid >> 5;
    const int lq   = lane >> 2;
    const int lr   = lane & 3;

    const size_t base = ((size_t)b * 3 * C_ + (size_t)h * HD) * L_;
    const uint16_t* Qp = (const uint16_t*)qkv + base;
    const uint16_t* Kp = Qp + (size_t)C_ * L_;
    const uint16_t* Vp = Qp + (size_t)2 * C_ * L_;

    uint32_t aQ[4][4];
    {
        const int qw = q0 + w * 16;
        #pragma unroll
        for (int c = 0; c < 4; c++) {
            const int d0 = c * 16 + 2 * lr;
            const uint16_t* qb = Qp + (size_t)d0 * L_ + qw;
            aQ[c][0] = (uint32_t)qb[lq]     | ((uint32_t)qb[(size_t)L_ + lq])     << 16;
            aQ[c][1] = (uint32_t)qb[lq + 8] | ((uint32_t)qb[(size_t)L_ + lq + 8]) << 16;
            const uint16_t* qc = qb + (size_t)8 * L_;
            aQ[c][2] = (uint32_t)qc[lq]     | ((uint32_t)qc[(size_t)L_ + lq])     << 16;
            aQ[c][3] = (uint32_t)qc[lq + 8] | ((uint32_t)qc[(size_t)L_ + lq + 8]) << 16;
        }
    }

    const int ld_d = tid >> 2;
    const int ld_c = (tid & 3);
    const uint16_t* kgp = Kp + (size_t)ld_d * L_ + k00 + ld_c * 8;
    const uint16_t* vgp = Vp + (size_t)ld_d * L_ + k00 + ld_c * 8;
    const uint32_t kds = sbase + ld_d * TPB + ld_c * 16;
    const uint32_t vds = sbase + 3 * TBUF + ld_d * TPB + ld_c * 16;

    const int mi = lane >> 3;
    const int r8 = lane & 7;
    const uint32_t kmat = sbase + ((mi & 1) * 8 + r8) * TPB + (mi >> 1) * 16;
    const uint32_t vmat = sbase + 3 * TBUF + ((mi >> 1) * 8 + r8) * TPB + (mi & 1) * 16;

    cpa16(kds,        kgp);       cpa16(vds,        vgp);       cpa_commit();
    cpa16(kds + TBUF, kgp + 32);  cpa16(vds + TBUF, vgp + 32);  cpa_commit();

    float O[8][4] = {};
    float Lacc[4] = {};
    int bc = 0, bn = 2;

    for (int t = 0; t < NT; t++) {
        cpa_wait<1>();
        __syncthreads();

        if (t < NT - 2) {
            const int off = (t + 2) * 32;
            cpa16(kds + bn * TBUF, kgp + off);
            cpa16(vds + bn * TBUF, vgp + off);
        }
        cpa_commit();

        const uint32_t kb = kmat + bc * TBUF;
        const uint32_t vb = vmat + bc * TBUF;

        float Sx[4][4] = {};
        #pragma unroll
        for (int c = 0; c < 4; c++) {
            uint32_t b00, b01, b10, b11;
            ldsm4t(b00, b01, b10, b11, kb + c * 16 * TPB);
            mma16(Sx[0], aQ[c], b00, b01);
            mma16(Sx[1], aQ[c], b10, b11);
            ldsm4t(b00, b01, b10, b11, kb + c * 16 * TPB + 32);
            mma16(Sx[2], aQ[c], b00, b01);
            mma16(Sx[3], aQ[c], b10, b11);
        }

        // P = 2^S in f16x2 (packed = PV A-fragment directly)
        #pragma unroll
        for (int kc = 0; kc < 2; kc++) {
            uint32_t aP[4];
            aP[0] = exp2_f16x2(Sx[2 * kc][0],     Sx[2 * kc][1]);
            aP[1] = exp2_f16x2(Sx[2 * kc][2],     Sx[2 * kc][3]);
            aP[2] = exp2_f16x2(Sx[2 * kc + 1][0], Sx[2 * kc + 1][1]);
            aP[3] = exp2_f16x2(Sx[2 * kc + 1][2], Sx[2 * kc + 1][3]);
            mma16h(Lacc, aP, ONES_F16X2, ONES_F16X2);
            #pragma unroll
            for (int g = 0; g < 4; g++) {
                uint32_t v00, v01, v10, v11;
                ldsm4(v00, v01, v10, v11, vb + g * 16 * TPB + kc * 32);
                mma16h(O[2 * g],     aP, v00, v01);
                mma16h(O[2 * g + 1], aP, v10, v11);
            }
        }

        bc = (bc == 2) ? 0 : bc + 1;
        bn = (bn == 2) ? 0 : bn + 1;
    }

    // publish row sums
    if (lr == 0) {
        float* lp = lsp + ((size_t)(sp * B_ + b) * NH + h) * L_ + q0 + w * 16;
        lp[lq]     = Lacc[0];
        lp[lq + 8] = Lacc[2];
    }

    // stage un-normalized O, write bf16 transposed
    __syncthreads();
    float* Os = reinterpret_cast<float*>(smu);   // [128 q][OP]
    #pragma unroll
    for (int dt = 0; dt < 8; dt++) {
        float* r0 = Os + (w * 16 + lq)     * OP + dt * 8 + 2 * lr;
        float* r1 = Os + (w * 16 + lq + 8) * OP + dt * 8 + 2 * lr;
        *reinterpret_cast<float2*>(r0) = make_float2(O[dt][0], O[dt][1]);
        *reinterpret_cast<float2*>(r1) = make_float2(O[dt][2], O[dt][3]);
    }
    __syncthreads();
    {
        __nv_bfloat16* Ob = osp + ((size_t)(sp * B_ + b) * C_ + (size_t)h * HD) * L_;
        const int d = tid >> 2, qc = (tid & 3) * 32;
        __nv_bfloat16* op = Ob + (size_t)d * L_ + q0 + qc;
        #pragma unroll
        for (int i = 0; i < 32; i += 4) {
            float4 v;
            v.x = Os[(qc + i + 0) * OP + d];
            v.y = Os[(qc + i + 1) * OP + d];
            v.z = Os[(qc + i + 2) * OP + d];
            v.w = Os[(qc + i + 3) * OP + d];
            uint2 pk;
            pk.x = pack_bf16(v.x, v.y);
            pk.y = pack_bf16(v.z, v.w);
            *reinterpret_cast<uint2*>(op + i) = pk;
        }
    }
}

// ---------------------------------------------------------------------------
// Combine: atth = (O0 + O1) / (l0 + l1); osp is bf16, l fp32. 8 elems/thread.
// ---------------------------------------------------------------------------
__global__ void attn_combine(const __nv_bfloat16* __restrict__ osp,
                             const float* __restrict__ lsp,
                             __nv_bfloat16* __restrict__ atth) {
    const uint32_t base = (blockIdx.x * 256 + threadIdx.x) * 8;
    const int l_idx = base & (L_ - 1);
    const int bcg = base >> 12;
    const int c = bcg & (C_ - 1);
    const int b = bcg >> 8;
    const int h = c >> 6;

    const uint4 a = *reinterpret_cast<const uint4*>(osp + base);
    const uint4 bb = *reinterpret_cast<const uint4*>(osp + (size_t)B_ * C_ * L_ + base);
    const float* l0 = lsp + ((size_t)b * NH + h) * L_ + l_idx;
    const float* l1 = l0 + (size_t)B_ * NH * L_;
    float4 s0 = *reinterpret_cast<const float4*>(l0);
    float4 s1 = *reinterpret_cast<const float4*>(l0 + 4);
    float4 t0 = *reinterpret_cast<const float4*>(l1);
    float4 t1 = *reinterpret_cast<const float4*>(l1 + 4);

    float r[8];
    r[0] = (bf_lo(a.x) + bf_lo(bb.x)) / (s0.x + t0.x);
    r[1] = (bf_hi(a.x) + bf_hi(bb.x)) / (s0.y + t0.y);
    r[2] = (bf_lo(a.y) + bf_lo(bb.y)) / (s0.z + t0.z);
    r[3] = (bf_hi(a.y) + bf_hi(bb.y)) / (s0.w + t0.w);
    r[4] = (bf_lo(a.z) + bf_lo(bb.z)) / (s1.x + t1.x);
    r[5] = (bf_hi(a.z) + bf_hi(bb.z)) / (s1.y + t1.y);
    r[6] = (bf_lo(a.w) + bf_lo(bb.w)) / (s1.z + t1.z);
    r[7] = (bf_hi(a.w) + bf_hi(bb.w)) / (s1.w + t1.w);

    uint4 pk;
    pk.x = pack_bf16(r[0], r[1]);
    pk.y = pack_bf16(r[2], r[3]);
    pk.z = pack_bf16(r[4], r[5]);
    pk.w = pack_bf16(r[6], r[7]);
    *reinterpret_cast<uint4*>(atth + base) = pk;
}

// ---------------------------------------------------------------------------
extern "C" void kernel_launch(void* const* d_in, const int* in_sizes, int n_in,
                              void* d_out, int out_size) {
    const float* x      = (const float*)d_in[0];
    const float* qkv_w  = (const float*)d_in[1];
    const float* qkv_b  = (const float*)d_in[2];
    const float* proj_w = (const float*)d_in[3];
    const float* proj_b = (const float*)d_in[4];
    const float* gamma  = (const float*)d_in[5];
    const float* beta   = (const float*)d_in[6];
    float* out = (float*)d_out;

    float *xn, *part, *lsp;
    __nv_bfloat16 *xnh, *qkvh, *atth, *wqh, *wph, *osp;
    cudaGetSymbolAddress((void**)&xn,   g_xn);
    cudaGetSymbolAddress((void**)&xnh,  g_xnh);
    cudaGetSymbolAddress((void**)&qkvh, g_qkvh);
    cudaGetSymbolAddress((void**)&atth, g_atth);
    cudaGetSymbolAddress((void**)&part, g_part);
    cudaGetSymbolAddress((void**)&wqh,  g_wqh);
    cudaGetSymbolAddress((void**)&wph,  g_wph);
    cudaGetSymbolAddress((void**)&osp,  g_osp);
    cudaGetSymbolAddress((void**)&lsp,  g_lsp);

    const int attn_smem = 128 * OP * (int)sizeof(float);   // 36864 B >= 6*TBUF

    gn_reduce<<<B_ * G_ * 8, 256>>>(x, part);
    gn_apply <<<B_ * G_ * 8, 256>>>(x, part, gamma, beta, xn, xnh,
                                    qkv_w, proj_w, wqh, wph);

    dim3 g_qkvgrid(L_ / 64, (3 * C_) / 128, B_);
    gemm_bf16<false, true><<<g_qkvgrid, 256>>>(wqh, qkv_b, xnh, qkvh, nullptr, 3 * C_, C_);

    dim3 g_attn(L_ / 128, NH, B_ * 2);
    attn_split<<<g_attn, 256, attn_smem>>>(qkvh, osp, lsp);

    attn_combine<<<(B_ * C_ * L_) / (256 * 8), 256>>>(osp, lsp, atth);

    dim3 g_proj(L_ / 64, C_ / 128, B_);
    gemm_bf16<true, false><<<g_proj, 256>>>(wph, proj_b, atth, out, xn, C_, C_);
}

// round 13
// speedup vs baseline: 1.2969x; 1.1126x over previous
#include <cuda_runtime.h>
#include <cuda_bf16.h>
#include <cuda_fp16.h>
#include <mma.h>
#include <math.h>
#include <stdint.h>

using namespace nvcuda;

#define B_   4
#define C_   256
#define L_   4096
#define G_   8
#define NH   4
#define HD   64
#define EPSV 1e-5f
#define EP   72    // gemm epilogue staging pitch (floats)
#define WP   40    // gemm W tile pitch (bf16)
#define XP   80    // gemm X tile pitch (bf16)
#define WBUF (128 * WP * 2)   // 10240 B
#define XBUF (32 * XP * 2)    //  5120 B
#define TPB  80    // attn tile row pitch (bytes)
#define TBUF (64 * TPB)       //  5120 B
#define OP   72    // attn O staging pitch (floats)
#define LOG2E 1.4426950408889634f
#define ONES_F16X2 0x3C003C00u

// Scratch (device globals)
__device__ float         g_xn  [B_ * C_ * L_];
__device__ __nv_bfloat16 g_xnh [B_ * C_ * L_];
__device__ __nv_bfloat16 g_qkvh[B_ * 3 * C_ * L_];   // Q,K bf16; V region holds fp16
__device__ __nv_bfloat16 g_atth[B_ * C_ * L_];
__device__ float         g_part[B_ * G_ * 8 * 2];
__device__ __nv_bfloat16 g_wqh [3 * C_ * C_];
__device__ __nv_bfloat16 g_wph [C_ * C_];
__device__ __nv_bfloat16 g_osp [2 * B_ * C_ * L_];   // split un-normalized O (bf16)
__device__ float         g_lsp [2 * B_ * NH * L_];   // split row sums

// ---------------------------------------------------------------------------
__device__ __forceinline__ uint32_t pack_bf16(float lo, float hi) {
    __nv_bfloat162 p = __floats2bfloat162_rn(lo, hi);
    return *reinterpret_cast<uint32_t*>(&p);
}
__device__ __forceinline__ uint32_t pack_f16(float lo, float hi) {
    __half2 p = __floats2half2_rn(lo, hi);
    return *reinterpret_cast<uint32_t*>(&p);
}
__device__ __forceinline__ uint32_t exp2_f16x2(float lo, float hi) {
    uint32_t p, r;
    asm("cvt.rn.f16x2.f32 %0, %1, %2;" : "=r"(p) : "f"(hi), "f"(lo));
    asm("ex2.approx.f16x2 %0, %1;" : "=r"(r) : "r"(p));
    return r;
}
__device__ __forceinline__ float bf_lo(uint32_t u) { return __uint_as_float(u << 16); }
__device__ __forceinline__ float bf_hi(uint32_t u) { return __uint_as_float(u & 0xFFFF0000u); }
__device__ __forceinline__ void mma16(float* d, const uint32_t* a, uint32_t b0, uint32_t b1) {
    asm volatile(
        "mma.sync.aligned.m16n8k16.row.col.f32.bf16.bf16.f32 "
        "{%0,%1,%2,%3}, {%4,%5,%6,%7}, {%8,%9}, {%0,%1,%2,%3};"
        : "+f"(d[0]), "+f"(d[1]), "+f"(d[2]), "+f"(d[3])
        : "r"(a[0]), "r"(a[1]), "r"(a[2]), "r"(a[3]), "r"(b0), "r"(b1));
}
__device__ __forceinline__ void mma16h(float* d, const uint32_t* a, uint32_t b0, uint32_t b1) {
    asm volatile(
        "mma.sync.aligned.m16n8k16.row.col.f32.f16.f16.f32 "
        "{%0,%1,%2,%3}, {%4,%5,%6,%7}, {%8,%9}, {%0,%1,%2,%3};"
        : "+f"(d[0]), "+f"(d[1]), "+f"(d[2]), "+f"(d[3])
        : "r"(a[0]), "r"(a[1]), "r"(a[2]), "r"(a[3]), "r"(b0), "r"(b1));
}
__device__ __forceinline__ void ldsm4(uint32_t& r0, uint32_t& r1, uint32_t& r2, uint32_t& r3,
                                      uint32_t saddr) {
    asm volatile("ldmatrix.sync.aligned.m8n8.x4.shared.b16 {%0,%1,%2,%3}, [%4];"
        : "=r"(r0), "=r"(r1), "=r"(r2), "=r"(r3) : "r"(saddr));
}
__device__ __forceinline__ void ldsm4t(uint32_t& r0, uint32_t& r1, uint32_t& r2, uint32_t& r3,
                                       uint32_t saddr) {
    asm volatile("ldmatrix.sync.aligned.m8n8.x4.trans.shared.b16 {%0,%1,%2,%3}, [%4];"
        : "=r"(r0), "=r"(r1), "=r"(r2), "=r"(r3) : "r"(saddr));
}
__device__ __forceinline__ void cpa16(uint32_t dst, const void* src) {
    asm volatile("cp.async.cg.shared.global [%0], [%1], 16;" :: "r"(dst), "l"(src));
}
__device__ __forceinline__ void cpa_commit() {
    asm volatile("cp.async.commit_group;");
}
template<int N>
__device__ __forceinline__ void cpa_wait() {
    asm volatile("cp.async.wait_group %0;" :: "n"(N));
}

// ---------------------------------------------------------------------------
// GroupNorm pass 1
// ---------------------------------------------------------------------------
__global__ void gn_reduce(const float* __restrict__ x, float* __restrict__ part) {
    const int blk = blockIdx.x;
    const int bg = blk >> 3, sub = blk & 7;
    const int SL = (C_ / G_) * L_ / 8;
    const float* xp = x + (size_t)bg * (C_ / G_) * L_ + (size_t)sub * SL;

    float s = 0.f, s2 = 0.f;
    for (int i = threadIdx.x * 4; i < SL; i += blockDim.x * 4) {
        float4 v = *reinterpret_cast<const float4*>(xp + i);
        s  += v.x + v.y + v.z + v.w;
        s2 += v.x * v.x + v.y * v.y + v.z * v.z + v.w * v.w;
    }
    #pragma unroll
    for (int o = 16; o; o >>= 1) {
        s  += __shfl_xor_sync(~0u, s,  o);
        s2 += __shfl_xor_sync(~0u, s2, o);
    }
    __shared__ float rs[8], rs2[8];
    const int wid = threadIdx.x >> 5;
    if ((threadIdx.x & 31) == 0) { rs[wid] = s; rs2[wid] = s2; }
    __syncthreads();
    if (threadIdx.x == 0) {
        float ts = 0.f, ts2 = 0.f;
        #pragma unroll
        for (int i = 0; i < 8; i++) { ts += rs[i]; ts2 += rs2[i]; }
        part[blk * 2 + 0] = ts;
        part[blk * 2 + 1] = ts2;
    }
}

// ---------------------------------------------------------------------------
// GroupNorm pass 2: fp32 xn + bf16 xnh; ALSO converts weights to bf16
// ---------------------------------------------------------------------------
__global__ void gn_apply(const float* __restrict__ x,
                         const float* __restrict__ part,
                         const float* __restrict__ gamma,
                         const float* __restrict__ beta,
                         float* __restrict__ xn,
                         __nv_bfloat16* __restrict__ xnh,
                         const float* __restrict__ qkv_w,
                         const float* __restrict__ proj_w,
                         __nv_bfloat16* __restrict__ wqh,
                         __nv_bfloat16* __restrict__ wph) {
    const int blk = blockIdx.x;
    const int bg = blk >> 3, sub = blk & 7;
    const int g = bg & (G_ - 1);
    const int SL = (C_ / G_) * L_ / 8;
    const int n = (C_ / G_) * L_;

    {
        const int wi = (blk * 256 + threadIdx.x) * 4;
        const float* src; __nv_bfloat16* dst; int off;
        if (wi < 3 * C_ * C_) { src = qkv_w; dst = wqh; off = wi; }
        else                  { src = proj_w; dst = wph; off = wi - 3 * C_ * C_; }
        float4 v = *reinterpret_cast<const float4*>(src + off);
        uint2 pk;
        pk.x = pack_bf16(v.x, v.y);
        pk.y = pack_bf16(v.z, v.w);
        *reinterpret_cast<uint2*>(dst + off) = pk;
    }

    float ts = 0.f, ts2 = 0.f;
    #pragma unroll
    for (int i = 0; i < 8; i++) {
        ts  += part[(bg * 8 + i) * 2 + 0];
        ts2 += part[(bg * 8 + i) * 2 + 1];
    }
    const float mean = ts / (float)n;
    const float inv  = rsqrtf(ts2 / (float)n - mean * mean + EPSV);

    const size_t base = (size_t)bg * (C_ / G_) * L_ + (size_t)sub * SL;
    const float* xp = x + base;
    float* yp = xn + base;
    __nv_bfloat16* hp = xnh + base;
    const int off0 = sub * SL;
    for (int i = threadIdx.x * 4; i < SL; i += blockDim.x * 4) {
        const int c = g * (C_ / G_) + ((off0 + i) >> 12);
        const float ga = gamma[c], be = beta[c];
        float4 v = *reinterpret_cast<const float4*>(xp + i);
        float4 o;
        o.x = (v.x - mean) * inv * ga + be;
        o.y = (v.y - mean) * inv * ga + be;
        o.z = (v.z - mean) * inv * ga + be;
        o.w = (v.w - mean) * inv * ga + be;
        *reinterpret_cast<float4*>(yp + i) = o;
        uint2 pk;
        pk.x = pack_bf16(o.x, o.y);
        pk.y = pack_bf16(o.z, o.w);
        *reinterpret_cast<uint2*>(hp + i) = pk;
    }
}

// ---------------------------------------------------------------------------
// bf16 wmma GEMM: 128m x 64n tile, 3-stage cp.async pipeline, 256 threads.
// ---------------------------------------------------------------------------
template<bool RESID, bool QKVOUT>
__global__ __launch_bounds__(256)
void gemm_bf16(const __nv_bfloat16* __restrict__ Wh,
               const float* __restrict__ bias,
               const __nv_bfloat16* __restrict__ X,
               void* __restrict__ Yv,
               const float* __restrict__ R,
               int Mtot, int KDIM) {
    const int n0 = blockIdx.x * 64;
    const int m0 = blockIdx.y * 128;
    const int b  = blockIdx.z;
    const __nv_bfloat16* Xb = X + (size_t)b * KDIM * L_;

    __shared__ uint8_t smraw[3 * (WBUF + XBUF)];
    const uint32_t sb = (uint32_t)__cvta_generic_to_shared(smraw);

    const int tid = threadIdx.x;
    const int wid = tid >> 5;
    const int wm = wid >> 1, wn = wid & 1;

    const int wr0 = tid >> 1, wk0 = (tid & 1) * 16;
    const int xr  = tid >> 3, xn8 = (tid & 7) * 8;

    const int NS = KDIM / 32;

    auto issue = [&](int s) {
        const int k0 = s * 32;
        const uint32_t wbase = sb + (s % 3) * WBUF;
        const uint32_t xbase = sb + 3 * WBUF + (s % 3) * XBUF;
        cpa16(wbase + (wr0 * WP + wk0) * 2,
              Wh + (size_t)(m0 + wr0) * KDIM + k0 + wk0);
        cpa16(wbase + (wr0 * WP + wk0 + 8) * 2,
              Wh + (size_t)(m0 + wr0) * KDIM + k0 + wk0 + 8);
        cpa16(xbase + (xr * XP + xn8) * 2,
              Xb + (size_t)(k0 + xr) * L_ + n0 + xn8);
    };

    wmma::fragment<wmma::accumulator, 16, 16, 16, float> c00, c01, c10, c11;
    wmma::fill_fragment(c00, 0.f); wmma::fill_fragment(c01, 0.f);
    wmma::fill_fragment(c10, 0.f); wmma::fill_fragment(c11, 0.f);

    issue(0); cpa_commit();
    issue(1); cpa_commit();

    for (int s = 0; s < NS; s++) {
        cpa_wait<1>();
        __syncthreads();
        if (s + 2 < NS) issue(s + 2);
        cpa_commit();

        const __nv_bfloat16* Ws = reinterpret_cast<const __nv_bfloat16*>(smraw + (s % 3) * WBUF);
        const __nv_bfloat16* Xs = reinterpret_cast<const __nv_bfloat16*>(smraw + 3 * WBUF + (s % 3) * XBUF);
        #pragma unroll
        for (int ks = 0; ks < 32; ks += 16) {
            wmma::fragment<wmma::matrix_a, 16, 16, 16, __nv_bfloat16, wmma::row_major> a0, a1;
            wmma::fragment<wmma::matrix_b, 16, 16, 16, __nv_bfloat16, wmma::row_major> b0, b1;
            wmma::load_matrix_sync(a0, &Ws[(wm * 32) * WP + ks], WP);
            wmma::load_matrix_sync(a1, &Ws[(wm * 32 + 16) * WP + ks], WP);
            wmma::load_matrix_sync(b0, &Xs[ks * XP + wn * 32], XP);
            wmma::load_matrix_sync(b1, &Xs[ks * XP + wn * 32 + 16], XP);
            wmma::mma_sync(c00, a0, b0, c00);
            wmma::mma_sync(c01, a0, b1, c01);
            wmma::mma_sync(c10, a1, b0, c10);
            wmma::mma_sync(c11, a1, b1, c11);
        }
    }
    __syncthreads();

    float* smf = reinterpret_cast<float*>(smraw);
    wmma::store_matrix_sync(&smf[(wm * 32)      * EP + wn * 32],      c00, EP, wmma::mem_row_major);
    wmma::store_matrix_sync(&smf[(wm * 32)      * EP + wn * 32 + 16], c01, EP, wmma::mem_row_major);
    wmma::store_matrix_sync(&smf[(wm * 32 + 16) * EP + wn * 32],      c10, EP, wmma::mem_row_major);
    wmma::store_matrix_sync(&smf[(wm * 32 + 16) * EP + wn * 32 + 16], c11, EP, wmma::mem_row_major);
    __syncthreads();
    {
        const int m = tid >> 1, nn = (tid & 1) * 32;
        const float bv = bias[m0 + m];
        const size_t orow = (size_t)(m0 + m) * L_ + n0 + nn;
        if (QKVOUT) {
            __nv_bfloat16* Ybh = (__nv_bfloat16*)Yv + (size_t)b * Mtot * L_;
            const bool isQ = (m0 + m < C_);
            const bool isV = (m0 + m >= 2 * C_);
            const float sc = isQ ? 0.125f * LOG2E : 1.0f;
            #pragma unroll
            for (int i = 0; i < 32; i += 4) {
                float4 v = *reinterpret_cast<const float4*>(&smf[m * EP + nn + i]);
                v.x = (v.x + bv) * sc; v.y = (v.y + bv) * sc;
                v.z = (v.z + bv) * sc; v.w = (v.w + bv) * sc;
                uint2 pk;
                if (isV) {
                    pk.x = pack_f16(v.x, v.y);
                    pk.y = pack_f16(v.z, v.w);
                } else {
                    pk.x = pack_bf16(v.x, v.y);
                    pk.y = pack_bf16(v.z, v.w);
                }
                *reinterpret_cast<uint2*>(Ybh + orow + i) = pk;
            }
        } else {
            float* Yb = (float*)Yv + (size_t)b * Mtot * L_;
            #pragma unroll
            for (int i = 0; i < 32; i += 4) {
                float4 v = *reinterpret_cast<const float4*>(&smf[m * EP + nn + i]);
                v.x += bv; v.y += bv; v.z += bv; v.w += bv;
                if (RESID) {
                    float4 r = *reinterpret_cast<const float4*>(&R[(size_t)b * Mtot * L_ + orow + i]);
                    v.x += r.x; v.y += r.y; v.z += r.z; v.w += r.w;
                }
                *reinterpret_cast<float4*>(Yb + orow + i) = v;
            }
        }
    }
}

// ---------------------------------------------------------------------------
// Flash attention split-K (KSPLIT=2): 128q CTAs, 4 warps x 32q each, 128 thr,
// occ 3. Each K/V fragment is loaded ONCE per warp and feeds both 16q groups
// (2x arithmetic intensity on shared memory vs 16q/warp).
// ---------------------------------------------------------------------------
__global__ __launch_bounds__(128, 3)
void attn_split(const __nv_bfloat16* __restrict__ qkv,
                __nv_bfloat16* __restrict__ osp, float* __restrict__ lsp) {
    const int q0 = blockIdx.x * 128;
    const int h  = blockIdx.y;
    const int bz = blockIdx.z;
    const int b  = bz >> 1, sp = bz & 1;
    const int k00 = sp * (L_ / 2);
    const int NT  = (L_ / 2) / 32;   // 64 tiles

    extern __shared__ uint32_t smu[];
    const uint32_t sbase = (uint32_t)__cvta_generic_to_shared(smu);

    const int tid  = threadIdx.x;
    const int lane = tid & 31;
    const int w    = tid >> 5;        // 0..3, warp owns q rows w*32..w*32+31
    const int lq   = lane >> 2;
    const int lr   = lane & 3;

    const size_t base = ((size_t)b * 3 * C_ + (size_t)h * HD) * L_;
    const uint16_t* Qp = (const uint16_t*)qkv + base;
    const uint16_t* Kp = Qp + (size_t)C_ * L_;
    const uint16_t* Vp = Qp + (size_t)2 * C_ * L_;

    // Q A-fragments: 2 q-groups x 4 k-chunks
    uint32_t aQ[2][4][4];
    #pragma unroll
    for (int gq = 0; gq < 2; gq++) {
        const int qw = q0 + w * 32 + gq * 16;
        #pragma unroll
        for (int c = 0; c < 4; c++) {
            const int d0 = c * 16 + 2 * lr;
            const uint16_t* qb = Qp + (size_t)d0 * L_ + qw;
            aQ[gq][c][0] = (uint32_t)qb[lq]     | ((uint32_t)qb[(size_t)L_ + lq])     << 16;
            aQ[gq][c][1] = (uint32_t)qb[lq + 8] | ((uint32_t)qb[(size_t)L_ + lq + 8]) << 16;
            const uint16_t* qc = qb + (size_t)8 * L_;
            aQ[gq][c][2] = (uint32_t)qc[lq]     | ((uint32_t)qc[(size_t)L_ + lq])     << 16;
            aQ[gq][c][3] = (uint32_t)qc[lq + 8] | ((uint32_t)qc[(size_t)L_ + lq + 8]) << 16;
        }
    }

    // loaders: 128 threads, 2 x 16B chunks each for K and V per tile
    const int ld_d = tid >> 1;
    const int ld_c = (tid & 1) * 2;
    const uint16_t* kgp = Kp + (size_t)ld_d * L_ + k00 + ld_c * 8;
    const uint16_t* vgp = Vp + (size_t)ld_d * L_ + k00 + ld_c * 8;
    const uint32_t kds = sbase + ld_d * TPB + ld_c * 16;
    const uint32_t vds = sbase + 3 * TBUF + ld_d * TPB + ld_c * 16;

    const int mi = lane >> 3;
    const int r8 = lane & 7;
    const uint32_t kmat = sbase + ((mi & 1) * 8 + r8) * TPB + (mi >> 1) * 16;
    const uint32_t vmat = sbase + 3 * TBUF + ((mi >> 1) * 8 + r8) * TPB + (mi & 1) * 16;

    // prologue tiles 0,1
    cpa16(kds, kgp);               cpa16(kds + 16, kgp + 8);
    cpa16(vds, vgp);               cpa16(vds + 16, vgp + 8);
    cpa_commit();
    cpa16(kds + TBUF, kgp + 32);   cpa16(kds + TBUF + 16, kgp + 40);
    cpa16(vds + TBUF, vgp + 32);   cpa16(vds + TBUF + 16, vgp + 40);
    cpa_commit();

    float O0[8][4] = {}, O1[8][4] = {};
    float La0[4] = {}, La1[4] = {};
    int bc = 0, bn = 2;

    for (int t = 0; t < NT; t++) {
        cpa_wait<1>();
        __syncthreads();

        if (t < NT - 2) {
            const int off = (t + 2) * 32;
            cpa16(kds + bn * TBUF,      kgp + off);
            cpa16(kds + bn * TBUF + 16, kgp + off + 8);
            cpa16(vds + bn * TBUF,      vgp + off);
            cpa16(vds + bn * TBUF + 16, vgp + off + 8);
        }
        cpa_commit();

        const uint32_t kb = kmat + bc * TBUF;
        const uint32_t vb = vmat + bc * TBUF;

        // S for both q-groups; each K fragment loaded once
        float S0[4][4] = {}, S1[4][4] = {};
        #pragma unroll
        for (int c = 0; c < 4; c++) {
            uint32_t b00, b01, b10, b11;
            ldsm4t(b00, b01, b10, b11, kb + c * 16 * TPB);
            mma16(S0[0], aQ[0][c], b00, b01);
            mma16(S0[1], aQ[0][c], b10, b11);
            mma16(S1[0], aQ[1][c], b00, b01);
            mma16(S1[1], aQ[1][c], b10, b11);
            ldsm4t(b00, b01, b10, b11, kb + c * 16 * TPB + 32);
            mma16(S0[2], aQ[0][c], b00, b01);
            mma16(S0[3], aQ[0][c], b10, b11);
            mma16(S1[2], aQ[1][c], b00, b01);
            mma16(S1[3], aQ[1][c], b10, b11);
        }

        // P = 2^S (f16x2); PV + l for both groups; each V fragment loaded once
        #pragma unroll
        for (int kc = 0; kc < 2; kc++) {
            uint32_t aP0[4], aP1[4];
            aP0[0] = exp2_f16x2(S0[2 * kc][0],     S0[2 * kc][1]);
            aP0[1] = exp2_f16x2(S0[2 * kc][2],     S0[2 * kc][3]);
            aP0[2] = exp2_f16x2(S0[2 * kc + 1][0], S0[2 * kc + 1][1]);
            aP0[3] = exp2_f16x2(S0[2 * kc + 1][2], S0[2 * kc + 1][3]);
            aP1[0] = exp2_f16x2(S1[2 * kc][0],     S1[2 * kc][1]);
            aP1[1] = exp2_f16x2(S1[2 * kc][2],     S1[2 * kc][3]);
            aP1[2] = exp2_f16x2(S1[2 * kc + 1][0], S1[2 * kc + 1][1]);
            aP1[3] = exp2_f16x2(S1[2 * kc + 1][2], S1[2 * kc + 1][3]);
            mma16h(La0, aP0, ONES_F16X2, ONES_F16X2);
            mma16h(La1, aP1, ONES_F16X2, ONES_F16X2);
            #pragma unroll
            for (int g = 0; g < 4; g++) {
                uint32_t v00, v01, v10, v11;
                ldsm4(v00, v01, v10, v11, vb + g * 16 * TPB + kc * 32);
                mma16h(O0[2 * g],     aP0, v00, v01);
                mma16h(O0[2 * g + 1], aP0, v10, v11);
                mma16h(O1[2 * g],     aP1, v00, v01);
                mma16h(O1[2 * g + 1], aP1, v10, v11);
            }
        }

        bc = (bc == 2) ? 0 : bc + 1;
        bn = (bn == 2) ? 0 : bn + 1;
    }

    // publish row sums
    if (lr == 0) {
        float* lp = lsp + ((size_t)(sp * B_ + b) * NH + h) * L_ + q0 + w * 32;
        lp[lq]          = La0[0];
        lp[lq + 8]      = La0[2];
        lp[16 + lq]     = La1[0];
        lp[16 + lq + 8] = La1[2];
    }

    // stage un-normalized O, write bf16 transposed
    __syncthreads();
    float* Os = reinterpret_cast<float*>(smu);   // [128 q][OP]
    #pragma unroll
    for (int dt = 0; dt < 8; dt++) {
        float* r0 = Os + (w * 32 + lq)      * OP + dt * 8 + 2 * lr;
        float* r1 = Os + (w * 32 + lq + 8)  * OP + dt * 8 + 2 * lr;
        float* r2 = Os + (w * 32 + 16 + lq) * OP + dt * 8 + 2 * lr;
        float* r3 = Os + (w * 32 + 24 + lq) * OP + dt * 8 + 2 * lr;
        *reinterpret_cast<float2*>(r0) = make_float2(O0[dt][0], O0[dt][1]);
        *reinterpret_cast<float2*>(r1) = make_float2(O0[dt][2], O0[dt][3]);
        *reinterpret_cast<float2*>(r2) = make_float2(O1[dt][0], O1[dt][1]);
        *reinterpret_cast<float2*>(r3) = make_float2(O1[dt][2], O1[dt][3]);
    }
    __syncthreads();
    {
        __nv_bfloat16* Ob = osp + ((size_t)(sp * B_ + b) * C_ + (size_t)h * HD) * L_;
        const int d = tid >> 1, qc = (tid & 1) * 64;
        __nv_bfloat16* op = Ob + (size_t)d * L_ + q0 + qc;
        #pragma unroll
        for (int i = 0; i < 64; i += 4) {
            float4 v;
            v.x = Os[(qc + i + 0) * OP + d];
            v.y = Os[(qc + i + 1) * OP + d];
            v.z = Os[(qc + i + 2) * OP + d];
            v.w = Os[(qc + i + 3) * OP + d];
            uint2 pk;
            pk.x = pack_bf16(v.x, v.y);
            pk.y = pack_bf16(v.z, v.w);
            *reinterpret_cast<uint2*>(op + i) = pk;
        }
    }
}

// ---------------------------------------------------------------------------
// Combine: atth = (O0 + O1) / (l0 + l1); osp bf16, l fp32.
// ---------------------------------------------------------------------------
__global__ void attn_combine(const __nv_bfloat16* __restrict__ osp,
                             const float* __restrict__ lsp,
                             __nv_bfloat16* __restrict__ atth) {
    const uint32_t base = (blockIdx.x * 256 + threadIdx.x) * 8;
    const int l_idx = base & (L_ - 1);
    const int bcg = base >> 12;
    const int c = bcg & (C_ - 1);
    const int b = bcg >> 8;
    const int h = c >> 6;

    const uint4 a = *reinterpret_cast<const uint4*>(osp + base);
    const uint4 bb = *reinterpret_cast<const uint4*>(osp + (size_t)B_ * C_ * L_ + base);
    const float* l0 = lsp + ((size_t)b * NH + h) * L_ + l_idx;
    const float* l1 = l0 + (size_t)B_ * NH * L_;
    float4 s0 = *reinterpret_cast<const float4*>(l0);
    float4 s1 = *reinterpret_cast<const float4*>(l0 + 4);
    float4 t0 = *reinterpret_cast<const float4*>(l1);
    float4 t1 = *reinterpret_cast<const float4*>(l1 + 4);

    float r[8];
    r[0] = (bf_lo(a.x) + bf_lo(bb.x)) / (s0.x + t0.x);
    r[1] = (bf_hi(a.x) + bf_hi(bb.x)) / (s0.y + t0.y);
    r[2] = (bf_lo(a.y) + bf_lo(bb.y)) / (s0.z + t0.z);
    r[3] = (bf_hi(a.y) + bf_hi(bb.y)) / (s0.w + t0.w);
    r[4] = (bf_lo(a.z) + bf_lo(bb.z)) / (s1.x + t1.x);
    r[5] = (bf_hi(a.z) + bf_hi(bb.z)) / (s1.y + t1.y);
    r[6] = (bf_lo(a.w) + bf_lo(bb.w)) / (s1.z + t1.z);
    r[7] = (bf_hi(a.w) + bf_hi(bb.w)) / (s1.w + t1.w);

    uint4 pk;
    pk.x = pack_bf16(r[0], r[1]);
    pk.y = pack_bf16(r[2], r[3]);
    pk.z = pack_bf16(r[4], r[5]);
    pk.w = pack_bf16(r[6], r[7]);
    *reinterpret_cast<uint4*>(atth + base) = pk;
}

// ---------------------------------------------------------------------------
extern "C" void kernel_launch(void* const* d_in, const int* in_sizes, int n_in,
                              void* d_out, int out_size) {
    const float* x      = (const float*)d_in[0];
    const float* qkv_w  = (const float*)d_in[1];
    const float* qkv_b  = (const float*)d_in[2];
    const float* proj_w = (const float*)d_in[3];
    const float* proj_b = (const float*)d_in[4];
    const float* gamma  = (const float*)d_in[5];
    const float* beta   = (const float*)d_in[6];
    float* out = (float*)d_out;

    float *xn, *part, *lsp;
    __nv_bfloat16 *xnh, *qkvh, *atth, *wqh, *wph, *osp;
    cudaGetSymbolAddress((void**)&xn,   g_xn);
    cudaGetSymbolAddress((void**)&xnh,  g_xnh);
    cudaGetSymbolAddress((void**)&qkvh, g_qkvh);
    cudaGetSymbolAddress((void**)&atth, g_atth);
    cudaGetSymbolAddress((void**)&part, g_part);
    cudaGetSymbolAddress((void**)&wqh,  g_wqh);
    cudaGetSymbolAddress((void**)&wph,  g_wph);
    cudaGetSymbolAddress((void**)&osp,  g_osp);
    cudaGetSymbolAddress((void**)&lsp,  g_lsp);

    const int attn_smem = 128 * OP * (int)sizeof(float);   // 36864 B >= 6*TBUF

    gn_reduce<<<B_ * G_ * 8, 256>>>(x, part);
    gn_apply <<<B_ * G_ * 8, 256>>>(x, part, gamma, beta, xn, xnh,
                                    qkv_w, proj_w, wqh, wph);

    dim3 g_qkvgrid(L_ / 64, (3 * C_) / 128, B_);
    gemm_bf16<false, true><<<g_qkvgrid, 256>>>(wqh, qkv_b, xnh, qkvh, nullptr, 3 * C_, C_);

    dim3 g_attn(L_ / 128, NH, B_ * 2);
    attn_split<<<g_attn, 128, attn_smem>>>(qkvh, osp, lsp);

    attn_combine<<<(B_ * C_ * L_) / (256 * 8), 256>>>(osp, lsp, atth);

    dim3 g_proj(L_ / 64, C_ / 128, B_);
    gemm_bf16<true, false><<<g_proj, 256>>>(wph, proj_b, atth, out, xn, C_, C_);
}